// round 1
// baseline (speedup 1.0000x reference)
#include <cuda_runtime.h>
#include <math.h>

#define T 2048
#define D 2048
#define H 16
#define HD 128
#define RD 64
#define KC 4

// ---------------- scratch (device globals: allowed, no allocation) ----------
__device__ float g_q[T * D];
__device__ float g_k[T * D];
__device__ float g_v[T * D];
__device__ float g_q2[T * D];   // [H][T][HD]
__device__ float g_k2[T * D];   // [H][T][HD]
__device__ float g_v2[T * D];   // [H][T][HD]
__device__ float g_attn[T * D]; // [T][D] (head-major channels)

// ---------------- GEMM (NT): C[m,n] = sum_k A[m,k] * B[n,k] ------------------
// 128x128 tile, BK=8, 256 threads, 8x8 register microtile, register prefetch.
// blockIdx.z selects among up to 3 (B,C) pairs so QKV runs as one launch.
__global__ __launch_bounds__(256, 2)
void sgemm_nt(const float* __restrict__ A,
              const float* __restrict__ B0, const float* __restrict__ B1,
              const float* __restrict__ B2,
              float* __restrict__ C0, float* __restrict__ C1,
              float* __restrict__ C2)
{
    const float* B = (blockIdx.z == 0) ? B0 : ((blockIdx.z == 1) ? B1 : B2);
    float*       C = (blockIdx.z == 0) ? C0 : ((blockIdx.z == 1) ? C1 : C2);

    __shared__ float As[8][132];
    __shared__ float Bs[8][132];

    const int tid  = threadIdx.x;
    const int brow = blockIdx.y * 128;
    const int bcol = blockIdx.x * 128;

    const int lr = tid >> 1;          // 0..127 row of tile
    const int lc = (tid & 1) * 4;     // 0 or 4 within K-slice
    const float* Ap = A + (size_t)(brow + lr) * D + lc;
    const float* Bp = B + (size_t)(bcol + lr) * D + lc;

    const int ty = tid >> 4;          // 0..15
    const int tx = tid & 15;          // 0..15

    float acc[8][8];
#pragma unroll
    for (int i = 0; i < 8; i++)
#pragma unroll
        for (int j = 0; j < 8; j++) acc[i][j] = 0.f;

    float4 av = *(const float4*)Ap;
    float4 bv = *(const float4*)Bp;

    for (int k0 = 0; k0 < D; k0 += 8) {
        As[lc + 0][lr] = av.x; As[lc + 1][lr] = av.y;
        As[lc + 2][lr] = av.z; As[lc + 3][lr] = av.w;
        Bs[lc + 0][lr] = bv.x; Bs[lc + 1][lr] = bv.y;
        Bs[lc + 2][lr] = bv.z; Bs[lc + 3][lr] = bv.w;
        __syncthreads();

        if (k0 + 8 < D) {
            av = *(const float4*)(Ap + k0 + 8);
            bv = *(const float4*)(Bp + k0 + 8);
        }

#pragma unroll
        for (int kk = 0; kk < 8; kk++) {
            float a[8], b[8];
            *(float4*)&a[0] = *(const float4*)&As[kk][ty * 8];
            *(float4*)&a[4] = *(const float4*)&As[kk][ty * 8 + 4];
            *(float4*)&b[0] = *(const float4*)&Bs[kk][tx * 8];
            *(float4*)&b[4] = *(const float4*)&Bs[kk][tx * 8 + 4];
#pragma unroll
            for (int i = 0; i < 8; i++)
#pragma unroll
                for (int j = 0; j < 8; j++)
                    acc[i][j] = fmaf(a[i], b[j], acc[i][j]);
        }
        __syncthreads();
    }

#pragma unroll
    for (int i = 0; i < 8; i++) {
        float* cp = C + (size_t)(brow + ty * 8 + i) * D + bcol + tx * 8;
        *(float4*)cp       = make_float4(acc[i][0], acc[i][1], acc[i][2], acc[i][3]);
        *(float4*)(cp + 4) = make_float4(acc[i][4], acc[i][5], acc[i][6], acc[i][7]);
    }
}

// -------- fused: causal conv(K=4)+SiLU, RMSNorm(q,k), RoPE, head transpose ---
// grid (T, H), block 128 (one thread per head-dim channel)
__global__ void fuse_post(const float* __restrict__ cosb,
                          const float* __restrict__ sinb,
                          const float* __restrict__ wq,
                          const float* __restrict__ wk,
                          const float* __restrict__ wv,
                          const float* __restrict__ qnw,
                          const float* __restrict__ knw)
{
    const int t  = blockIdx.x;
    const int h  = blockIdx.y;
    const int hd = threadIdx.x;
    const int d  = h * HD + hd;

    float yq = 0.f, yk = 0.f, yv = 0.f;
#pragma unroll
    for (int j = 0; j < KC; j++) {
        int tt = t - (KC - 1) + j;
        if (tt >= 0) {
            size_t o = (size_t)tt * D + d;
            yq = fmaf(g_q[o], wq[d * KC + j], yq);
            yk = fmaf(g_k[o], wk[d * KC + j], yk);
            yv = fmaf(g_v[o], wv[d * KC + j], yv);
        }
    }
    // SiLU
    yq = yq / (1.f + __expf(-yq));
    yk = yk / (1.f + __expf(-yk));
    yv = yv / (1.f + __expf(-yv));

    // RMS stats over 128 channels of this head
    float vq = yq * yq, vk = yk * yk;
#pragma unroll
    for (int off = 16; off > 0; off >>= 1) {
        vq += __shfl_xor_sync(0xffffffffu, vq, off);
        vk += __shfl_xor_sync(0xffffffffu, vk, off);
    }
    __shared__ float rq[4], rk[4], sq[HD], sk[HD];
    const int w = hd >> 5;
    if ((hd & 31) == 0) { rq[w] = vq; rk[w] = vk; }
    __syncthreads();
    const float varq = (rq[0] + rq[1] + rq[2] + rq[3]) * (1.f / HD);
    const float vark = (rk[0] + rk[1] + rk[2] + rk[3]) * (1.f / HD);
    sq[hd] = yq * rsqrtf(varq + 1e-5f) * qnw[hd];
    sk[hd] = yk * rsqrtf(vark + 1e-5f) * knw[hd];
    __syncthreads();

    // RoPE: x_rot' = x_rot*cos + rotate_half(x_rot)*sin ; out = [-x_rot', x_pass]
    float oq, ok;
    if (hd < RD) {
        const float cs = cosb[t * RD + hd];
        const float sn = sinb[t * RD + hd];
        const float rqv = (hd < RD / 2) ? -sq[hd + RD / 2] : sq[hd - RD / 2];
        const float rkv = (hd < RD / 2) ? -sk[hd + RD / 2] : sk[hd - RD / 2];
        oq = -(sq[hd] * cs + rqv * sn);
        ok = -(sk[hd] * cs + rkv * sn);
    } else {
        oq = sq[hd];
        ok = sk[hd];
    }
    const size_t o = ((size_t)h * T + t) * HD + hd;
    g_q2[o] = oq; g_k2[o] = ok; g_v2[o] = yv;
}

// ---------------- causal flash attention, fp32 -------------------------------
// grid (T/64, H), 256 threads. 64x64 tiles.
// Thread: 2 rows (rp=tid>>3) x 8 cols (cg=tid&7, c=cg+8j) of scores;
// P.V: 2 rows x 16 output channels (cg*16..cg*16+15).
__global__ __launch_bounds__(256, 2)
void flash_attn()
{
    extern __shared__ float sh[];
    float* Qs = sh;                 // [64][132]
    float* Ks = sh + 64 * 132;      // [64][132]
    float* Vs = sh + 2 * 64 * 132;  // [64][132]

    const int h   = blockIdx.y;
    const int qt  = blockIdx.x;
    const int q0  = qt * 64;
    const int tid = threadIdx.x;
    const int cg  = tid & 7;
    const int rp  = tid >> 3;  // 0..31
    const int r0  = rp * 2, r1 = r0 + 1;

    const float* Qg = g_q2 + ((size_t)h * T + q0) * HD;
    const float* Kg = g_k2 + (size_t)h * T * HD;
    const float* Vg = g_v2 + (size_t)h * T * HD;

#pragma unroll
    for (int i = 0; i < 8; i++) {
        int idx = tid + i * 256;            // 2048 float4 slots
        int r   = idx >> 5;
        int c4  = (idx & 31) << 2;
        *(float4*)&Qs[r * 132 + c4] = *(const float4*)(Qg + r * HD + c4);
    }

    float m0 = -1e30f, m1 = -1e30f, l0 = 0.f, l1 = 0.f;
    float acc0[16], acc1[16];
#pragma unroll
    for (int i = 0; i < 16; i++) { acc0[i] = 0.f; acc1[i] = 0.f; }

    const float scale = 0.08838834764831845f;  // 1/sqrt(128)

    for (int kt = 0; kt <= qt; kt++) {
        const int k0 = kt * 64;
        __syncthreads();
#pragma unroll
        for (int i = 0; i < 8; i++) {
            int idx = tid + i * 256;
            int r   = idx >> 5;
            int c4  = (idx & 31) << 2;
            *(float4*)&Ks[r * 132 + c4] = *(const float4*)(Kg + (size_t)(k0 + r) * HD + c4);
            *(float4*)&Vs[r * 132 + c4] = *(const float4*)(Vg + (size_t)(k0 + r) * HD + c4);
        }
        __syncthreads();

        // scores
        float s0[8], s1[8];
#pragma unroll
        for (int j = 0; j < 8; j++) { s0[j] = 0.f; s1[j] = 0.f; }
#pragma unroll 8
        for (int kk = 0; kk < HD; kk += 4) {
            float4 qa = *(const float4*)&Qs[r0 * 132 + kk];
            float4 qb = *(const float4*)&Qs[r1 * 132 + kk];
#pragma unroll
            for (int j = 0; j < 8; j++) {
                float4 kv = *(const float4*)&Ks[(cg + j * 8) * 132 + kk];
                s0[j] = fmaf(qa.x, kv.x, fmaf(qa.y, kv.y, fmaf(qa.z, kv.z, fmaf(qa.w, kv.w, s0[j]))));
                s1[j] = fmaf(qb.x, kv.x, fmaf(qb.y, kv.y, fmaf(qb.z, kv.z, fmaf(qb.w, kv.w, s1[j]))));
            }
        }

        // mask + scale + row max
        float mx0 = -1e30f, mx1 = -1e30f;
#pragma unroll
        for (int j = 0; j < 8; j++) {
            int c = k0 + cg + j * 8;
            s0[j] = (c <= q0 + r0) ? s0[j] * scale : -1e30f;
            s1[j] = (c <= q0 + r1) ? s1[j] * scale : -1e30f;
            mx0 = fmaxf(mx0, s0[j]);
            mx1 = fmaxf(mx1, s1[j]);
        }
#pragma unroll
        for (int off = 1; off < 8; off <<= 1) {
            mx0 = fmaxf(mx0, __shfl_xor_sync(0xffffffffu, mx0, off));
            mx1 = fmaxf(mx1, __shfl_xor_sync(0xffffffffu, mx1, off));
        }
        const float mn0 = fmaxf(m0, mx0), mn1 = fmaxf(m1, mx1);
        const float c0 = __expf(m0 - mn0), c1 = __expf(m1 - mn1);
        float p0[8], p1[8];
        float ps0 = 0.f, ps1 = 0.f;
#pragma unroll
        for (int j = 0; j < 8; j++) {
            p0[j] = __expf(s0[j] - mn0); ps0 += p0[j];
            p1[j] = __expf(s1[j] - mn1); ps1 += p1[j];
        }
#pragma unroll
        for (int off = 1; off < 8; off <<= 1) {
            ps0 += __shfl_xor_sync(0xffffffffu, ps0, off);
            ps1 += __shfl_xor_sync(0xffffffffu, ps1, off);
        }
        l0 = l0 * c0 + ps0; l1 = l1 * c1 + ps1;
        m0 = mn0; m1 = mn1;
#pragma unroll
        for (int i = 0; i < 16; i++) { acc0[i] *= c0; acc1[i] *= c1; }

        // P @ V
#pragma unroll
        for (int j = 0; j < 8; j++) {
#pragma unroll
            for (int kk2 = 0; kk2 < 8; kk2++) {
                const int k   = j * 8 + kk2;
                const int src = (tid & 24) | kk2;  // lane holding P[r][k] for my rows
                const float pa = __shfl_sync(0xffffffffu, p0[j], src);
                const float pb = __shfl_sync(0xffffffffu, p1[j], src);
                const float4* vr = (const float4*)&Vs[k * 132 + cg * 16];
#pragma unroll
                for (int i = 0; i < 4; i++) {
                    float4 vv = vr[i];
                    acc0[i * 4 + 0] = fmaf(pa, vv.x, acc0[i * 4 + 0]);
                    acc0[i * 4 + 1] = fmaf(pa, vv.y, acc0[i * 4 + 1]);
                    acc0[i * 4 + 2] = fmaf(pa, vv.z, acc0[i * 4 + 2]);
                    acc0[i * 4 + 3] = fmaf(pa, vv.w, acc0[i * 4 + 3]);
                    acc1[i * 4 + 0] = fmaf(pb, vv.x, acc1[i * 4 + 0]);
                    acc1[i * 4 + 1] = fmaf(pb, vv.y, acc1[i * 4 + 1]);
                    acc1[i * 4 + 2] = fmaf(pb, vv.z, acc1[i * 4 + 2]);
                    acc1[i * 4 + 3] = fmaf(pb, vv.w, acc1[i * 4 + 3]);
                }
            }
        }
    }

    const float il0 = 1.f / l0, il1 = 1.f / l1;
    float* O0 = g_attn + (size_t)(q0 + r0) * D + h * HD + cg * 16;
    float* O1 = g_attn + (size_t)(q0 + r1) * D + h * HD + cg * 16;
#pragma unroll
    for (int i = 0; i < 4; i++) {
        *(float4*)(O0 + i * 4) = make_float4(acc0[i * 4] * il0, acc0[i * 4 + 1] * il0,
                                             acc0[i * 4 + 2] * il0, acc0[i * 4 + 3] * il0);
        *(float4*)(O1 + i * 4) = make_float4(acc1[i * 4] * il1, acc1[i * 4 + 1] * il1,
                                             acc1[i * 4 + 2] * il1, acc1[i * 4 + 3] * il1);
    }
}

// -----------------------------------------------------------------------------
extern "C" void kernel_launch(void* const* d_in, const int* in_sizes, int n_in,
                              void* d_out, int out_size)
{
    const float* x    = (const float*)d_in[0];
    const float* cosb = (const float*)d_in[1];
    const float* sinb = (const float*)d_in[2];
    const float* Wq   = (const float*)d_in[3];
    const float* Wk   = (const float*)d_in[4];
    const float* Wv   = (const float*)d_in[5];
    const float* Wo   = (const float*)d_in[6];
    const float* wq   = (const float*)d_in[7];
    const float* wk   = (const float*)d_in[8];
    const float* wv   = (const float*)d_in[9];
    const float* qnw  = (const float*)d_in[10];
    const float* knw  = (const float*)d_in[11];
    float* out = (float*)d_out;

    float *pq, *pk, *pv, *pattn;
    cudaGetSymbolAddress((void**)&pq, g_q);
    cudaGetSymbolAddress((void**)&pk, g_k);
    cudaGetSymbolAddress((void**)&pv, g_v);
    cudaGetSymbolAddress((void**)&pattn, g_attn);

    // 1) QKV projections (one batched launch)
    sgemm_nt<<<dim3(D / 128, T / 128, 3), 256>>>(x, Wq, Wk, Wv, pq, pk, pv);

    // 2) conv + SiLU + RMSNorm + RoPE + head transpose
    fuse_post<<<dim3(T, H), HD>>>(cosb, sinb, wq, wk, wv, qnw, knw);

    // 3) causal flash attention
    const int smem = 3 * 64 * 132 * (int)sizeof(float);
    cudaFuncSetAttribute(flash_attn, cudaFuncAttributeMaxDynamicSharedMemorySize, smem);
    flash_attn<<<dim3(T / 64, H), 256, smem>>>();

    // 4) output projection -> d_out
    sgemm_nt<<<dim3(D / 128, T / 128, 1), 256>>>(pattn, Wo, Wo, Wo, out, out, out);
}

// round 3
// speedup vs baseline: 1.3278x; 1.3278x over previous
#include <cuda_runtime.h>
#include <cuda_bf16.h>
#include <math.h>
#include <stdint.h>

#define T 2048
#define D 2048
#define H 16
#define HD 128
#define RD 64
#define KC 4

// ---------------- scratch (device globals) -----------------------------------
__device__ float g_q[T * D];
__device__ float g_k[T * D];
__device__ float g_v[T * D];
__device__ float g_q2[T * D];   // [H][T][HD]
__device__ float g_k2[T * D];   // [H][T][HD]
__device__ float g_v2[T * D];   // [H][T][HD]
__device__ float g_attn[T * D]; // [T][D]

__device__ __nv_bfloat16 g_xh[T * D], g_xl[T * D];
__device__ __nv_bfloat16 g_wh[4][D * D], g_wl[4][D * D];  // Wq,Wk,Wv,Wo
__device__ __nv_bfloat16 g_ah[T * D], g_al[T * D];

// ---------------- PTX helpers (baseline compute_103: mma.sync/ldmatrix/cp.async)
__device__ __forceinline__ uint32_t smem_u32(const void* p) {
    uint32_t a;
    asm("{ .reg .u64 t; cvta.to.shared.u64 t, %1; cvt.u32.u64 %0, t; }" : "=r"(a) : "l"(p));
    return a;
}

#define CP16(dst, src) \
    asm volatile("cp.async.cg.shared.global [%0], [%1], 16;" :: "r"(dst), "l"(src))
#define CP_COMMIT() asm volatile("cp.async.commit_group;" ::: "memory")
#define CP_WAIT(n)  asm volatile("cp.async.wait_group %0;" :: "n"(n) : "memory")

#define LDSM4(r0, r1, r2, r3, addr)                                      \
    asm volatile("ldmatrix.sync.aligned.m8n8.x4.shared.b16 {%0,%1,%2,%3}, [%4];" \
        : "=r"(r0), "=r"(r1), "=r"(r2), "=r"(r3) : "r"(addr))

#define MMA16816(d, a, b)                                                \
    asm volatile("mma.sync.aligned.m16n8k16.row.col.f32.bf16.bf16.f32 "  \
        "{%0,%1,%2,%3}, {%4,%5,%6,%7}, {%8,%9}, {%0,%1,%2,%3};"          \
        : "+f"((d)[0]), "+f"((d)[1]), "+f"((d)[2]), "+f"((d)[3])         \
        : "r"((a)[0]), "r"((a)[1]), "r"((a)[2]), "r"((a)[3]),            \
          "r"((b)[0]), "r"((b)[1]))

// ---------------- fp32 -> bf16 hi/lo split ------------------------------------
// z selects among up to 5 (src,hi,lo) triples.
__global__ void split_bf16(const float* __restrict__ s0, __nv_bfloat16* h0, __nv_bfloat16* l0,
                           const float* __restrict__ s1, __nv_bfloat16* h1, __nv_bfloat16* l1,
                           const float* __restrict__ s2, __nv_bfloat16* h2, __nv_bfloat16* l2,
                           const float* __restrict__ s3, __nv_bfloat16* h3, __nv_bfloat16* l3,
                           const float* __restrict__ s4, __nv_bfloat16* h4, __nv_bfloat16* l4)
{
    const float* s; __nv_bfloat16 *h, *l;
    switch (blockIdx.z) {
        case 0:  s = s0; h = h0; l = l0; break;
        case 1:  s = s1; h = h1; l = l1; break;
        case 2:  s = s2; h = h2; l = l2; break;
        case 3:  s = s3; h = h3; l = l3; break;
        default: s = s4; h = h4; l = l4; break;
    }
    const int n4 = T * D / 4;
    for (int i = blockIdx.x * blockDim.x + threadIdx.x; i < n4; i += gridDim.x * blockDim.x) {
        float4 v = ((const float4*)s)[i];
        __nv_bfloat162 h01 = __floats2bfloat162_rn(v.x, v.y);
        __nv_bfloat162 h23 = __floats2bfloat162_rn(v.z, v.w);
        __nv_bfloat162 l01 = __floats2bfloat162_rn(v.x - __low2float(h01), v.y - __high2float(h01));
        __nv_bfloat162 l23 = __floats2bfloat162_rn(v.z - __low2float(h23), v.w - __high2float(h23));
        ((__nv_bfloat162*)h)[2 * i]     = h01;
        ((__nv_bfloat162*)h)[2 * i + 1] = h23;
        ((__nv_bfloat162*)l)[2 * i]     = l01;
        ((__nv_bfloat162*)l)[2 * i + 1] = l23;
    }
}

// ---------------- bf16-split GEMM (NT): C[m,n] = sum_k A[m,k]*B[n,k] ----------
// 128x128 CTA tile, BK=32, 3-stage cp.async pipeline, mma.sync m16n8k16,
// 3 passes (ah*bh + ah*bl + al*bh) for ~fp32 accuracy. blockIdx.z picks B/C.
#define BK      32
#define NCK     (D / BK)          // 64
#define SROW    40                // bf16 units per smem row (80B, conflict-free)
#define TILE_E  (128 * SROW)      // 5120 elems
#define STAGE_E (4 * TILE_E)      // Ah,Al,Bh,Bl
#define GEMM_SMEM (3 * STAGE_E * 2)  // 122880 bytes

__global__ __launch_bounds__(256, 1)
void gemm_bf16s(const __nv_bfloat16* __restrict__ Ah_, const __nv_bfloat16* __restrict__ Al_,
                const __nv_bfloat16* __restrict__ Bh0, const __nv_bfloat16* __restrict__ Bl0,
                const __nv_bfloat16* __restrict__ Bh1, const __nv_bfloat16* __restrict__ Bl1,
                const __nv_bfloat16* __restrict__ Bh2, const __nv_bfloat16* __restrict__ Bl2,
                float* __restrict__ C0, float* __restrict__ C1, float* __restrict__ C2)
{
    const __nv_bfloat16* Bh_ = (blockIdx.z == 0) ? Bh0 : ((blockIdx.z == 1) ? Bh1 : Bh2);
    const __nv_bfloat16* Bl_ = (blockIdx.z == 0) ? Bl0 : ((blockIdx.z == 1) ? Bl1 : Bl2);
    float*               C   = (blockIdx.z == 0) ? C0  : ((blockIdx.z == 1) ? C1  : C2);

    extern __shared__ __nv_bfloat16 sm[];
    const uint32_t sbase = smem_u32(sm);

    const int tid  = threadIdx.x;
    const int lane = tid & 31;
    const int warp = tid >> 5;
    const int wm0  = (warp & 3) * 32;   // 4 warps along M
    const int wn0  = (warp >> 2) * 64;  // 2 warps along N
    const int brow = blockIdx.y * 128;
    const int bcol = blockIdx.x * 128;

    // cp.async slots: thread covers rows rld, rld+64 at 16B chunk cld
    const int rld = tid >> 2;   // 0..63
    const int cld = tid & 3;    // 0..3 -> k offset cld*8 elems

    auto load_chunk = [&](int c, int slot) {
        const int k0 = c * BK;
        const uint32_t s0 = sbase + (uint32_t)slot * (STAGE_E * 2);
#pragma unroll
        for (int t = 0; t < 2; t++) {
            const int r = rld + t * 64;
            const uint32_t so = s0 + 2 * (r * SROW + cld * 8);
            const size_t ga = (size_t)(brow + r) * D + k0 + cld * 8;
            const size_t gb = (size_t)(bcol + r) * D + k0 + cld * 8;
            CP16(so,              Ah_ + ga);
            CP16(so + 2 * TILE_E, Al_ + ga);
            CP16(so + 4 * TILE_E, Bh_ + gb);
            CP16(so + 6 * TILE_E, Bl_ + gb);
        }
    };

    float acc[2][8][4];
#pragma unroll
    for (int mt = 0; mt < 2; mt++)
#pragma unroll
        for (int nt = 0; nt < 8; nt++)
#pragma unroll
            for (int i = 0; i < 4; i++) acc[mt][nt][i] = 0.f;

    load_chunk(0, 0); CP_COMMIT();
    load_chunk(1, 1); CP_COMMIT();

    // fragment address components
    const int arow = wm0 + (lane & 15);
    const int akof = (lane >> 4) << 3;
    const int nrow = wn0 + (lane & 7) + ((lane & 16) >> 1);
    const int bkof = lane & 8;

    for (int c = 0; c < NCK; c++) {
        CP_WAIT(1);
        __syncthreads();
        if (c + 2 < NCK) load_chunk(c + 2, (c + 2) % 3);
        CP_COMMIT();

        const uint32_t sb = sbase + (uint32_t)(c % 3) * (STAGE_E * 2);
#pragma unroll
        for (int ks = 0; ks < 2; ks++) {
            const int kb = ks << 4;
            uint32_t ah[2][4], al[2][4], bh[8][2], bl[8][2];
#pragma unroll
            for (int mt = 0; mt < 2; mt++) {
                const uint32_t ad = sb + 2 * ((arow + mt * 16) * SROW + kb + akof);
                LDSM4(ah[mt][0], ah[mt][1], ah[mt][2], ah[mt][3], ad);
                LDSM4(al[mt][0], al[mt][1], al[mt][2], al[mt][3], ad + 2 * TILE_E);
            }
#pragma unroll
            for (int np = 0; np < 4; np++) {
                const uint32_t bd = sb + 2 * (2 * TILE_E + (nrow + np * 16) * SROW + kb + bkof);
                LDSM4(bh[2 * np][0], bh[2 * np][1], bh[2 * np + 1][0], bh[2 * np + 1][1], bd);
                LDSM4(bl[2 * np][0], bl[2 * np][1], bl[2 * np + 1][0], bl[2 * np + 1][1],
                      bd + 2 * TILE_E);
            }
#pragma unroll
            for (int mt = 0; mt < 2; mt++)
#pragma unroll
                for (int nt = 0; nt < 8; nt++) {
                    MMA16816(acc[mt][nt], ah[mt], bh[nt]);
                    MMA16816(acc[mt][nt], ah[mt], bl[nt]);
                    MMA16816(acc[mt][nt], al[mt], bh[nt]);
                }
        }
    }

    // epilogue: direct fp32 stores
#pragma unroll
    for (int mt = 0; mt < 2; mt++) {
        const int row = brow + wm0 + mt * 16 + (lane >> 2);
#pragma unroll
        for (int nt = 0; nt < 8; nt++) {
            const int col = bcol + wn0 + nt * 8 + 2 * (lane & 3);
            float* p = C + (size_t)row * D + col;
            p[0] = acc[mt][nt][0];
            p[1] = acc[mt][nt][1];
            p += 8 * (size_t)D;
            p[0] = acc[mt][nt][2];
            p[1] = acc[mt][nt][3];
        }
    }
}

// -------- fused: causal conv(K=4)+SiLU, RMSNorm(q,k), RoPE, head transpose ---
__global__ void fuse_post(const float* __restrict__ cosb,
                          const float* __restrict__ sinb,
                          const float* __restrict__ wq,
                          const float* __restrict__ wk,
                          const float* __restrict__ wv,
                          const float* __restrict__ qnw,
                          const float* __restrict__ knw)
{
    const int t  = blockIdx.x;
    const int h  = blockIdx.y;
    const int hd = threadIdx.x;
    const int d  = h * HD + hd;

    float yq = 0.f, yk = 0.f, yv = 0.f;
#pragma unroll
    for (int j = 0; j < KC; j++) {
        int tt = t - (KC - 1) + j;
        if (tt >= 0) {
            size_t o = (size_t)tt * D + d;
            yq = fmaf(g_q[o], wq[d * KC + j], yq);
            yk = fmaf(g_k[o], wk[d * KC + j], yk);
            yv = fmaf(g_v[o], wv[d * KC + j], yv);
        }
    }
    yq = yq / (1.f + __expf(-yq));
    yk = yk / (1.f + __expf(-yk));
    yv = yv / (1.f + __expf(-yv));

    float vq = yq * yq, vk = yk * yk;
#pragma unroll
    for (int off = 16; off > 0; off >>= 1) {
        vq += __shfl_xor_sync(0xffffffffu, vq, off);
        vk += __shfl_xor_sync(0xffffffffu, vk, off);
    }
    __shared__ float rq[4], rk[4], sq[HD], sk[HD];
    const int w = hd >> 5;
    if ((hd & 31) == 0) { rq[w] = vq; rk[w] = vk; }
    __syncthreads();
    const float varq = (rq[0] + rq[1] + rq[2] + rq[3]) * (1.f / HD);
    const float vark = (rk[0] + rk[1] + rk[2] + rk[3]) * (1.f / HD);
    sq[hd] = yq * rsqrtf(varq + 1e-5f) * qnw[hd];
    sk[hd] = yk * rsqrtf(vark + 1e-5f) * knw[hd];
    __syncthreads();

    float oq, ok;
    if (hd < RD) {
        const float cs = cosb[t * RD + hd];
        const float sn = sinb[t * RD + hd];
        const float rqv = (hd < RD / 2) ? -sq[hd + RD / 2] : sq[hd - RD / 2];
        const float rkv = (hd < RD / 2) ? -sk[hd + RD / 2] : sk[hd - RD / 2];
        oq = -(sq[hd] * cs + rqv * sn);
        ok = -(sk[hd] * cs + rkv * sn);
    } else {
        oq = sq[hd];
        ok = sk[hd];
    }
    const size_t o = ((size_t)h * T + t) * HD + hd;
    g_q2[o] = oq; g_k2[o] = ok; g_v2[o] = yv;
}

// ---------------- causal flash attention, fp32 (unchanged) -------------------
__global__ __launch_bounds__(256, 2)
void flash_attn()
{
    extern __shared__ float sh[];
    float* Qs = sh;
    float* Ks = sh + 64 * 132;
    float* Vs = sh + 2 * 64 * 132;

    const int h   = blockIdx.y;
    const int qt  = blockIdx.x;
    const int q0  = qt * 64;
    const int tid = threadIdx.x;
    const int cg  = tid & 7;
    const int rp  = tid >> 3;
    const int r0  = rp * 2, r1 = r0 + 1;

    const float* Qg = g_q2 + ((size_t)h * T + q0) * HD;
    const float* Kg = g_k2 + (size_t)h * T * HD;
    const float* Vg = g_v2 + (size_t)h * T * HD;

#pragma unroll
    for (int i = 0; i < 8; i++) {
        int idx = tid + i * 256;
        int r   = idx >> 5;
        int c4  = (idx & 31) << 2;
        *(float4*)&Qs[r * 132 + c4] = *(const float4*)(Qg + r * HD + c4);
    }

    float m0 = -1e30f, m1 = -1e30f, l0 = 0.f, l1 = 0.f;
    float acc0[16], acc1[16];
#pragma unroll
    for (int i = 0; i < 16; i++) { acc0[i] = 0.f; acc1[i] = 0.f; }

    const float scale = 0.08838834764831845f;

    for (int kt = 0; kt <= qt; kt++) {
        const int k0 = kt * 64;
        __syncthreads();
#pragma unroll
        for (int i = 0; i < 8; i++) {
            int idx = tid + i * 256;
            int r   = idx >> 5;
            int c4  = (idx & 31) << 2;
            *(float4*)&Ks[r * 132 + c4] = *(const float4*)(Kg + (size_t)(k0 + r) * HD + c4);
            *(float4*)&Vs[r * 132 + c4] = *(const float4*)(Vg + (size_t)(k0 + r) * HD + c4);
        }
        __syncthreads();

        float s0[8], s1[8];
#pragma unroll
        for (int j = 0; j < 8; j++) { s0[j] = 0.f; s1[j] = 0.f; }
#pragma unroll 8
        for (int kk = 0; kk < HD; kk += 4) {
            float4 qa = *(const float4*)&Qs[r0 * 132 + kk];
            float4 qb = *(const float4*)&Qs[r1 * 132 + kk];
#pragma unroll
            for (int j = 0; j < 8; j++) {
                float4 kv = *(const float4*)&Ks[(cg + j * 8) * 132 + kk];
                s0[j] = fmaf(qa.x, kv.x, fmaf(qa.y, kv.y, fmaf(qa.z, kv.z, fmaf(qa.w, kv.w, s0[j]))));
                s1[j] = fmaf(qb.x, kv.x, fmaf(qb.y, kv.y, fmaf(qb.z, kv.z, fmaf(qb.w, kv.w, s1[j]))));
            }
        }

        float mx0 = -1e30f, mx1 = -1e30f;
#pragma unroll
        for (int j = 0; j < 8; j++) {
            int c = k0 + cg + j * 8;
            s0[j] = (c <= q0 + r0) ? s0[j] * scale : -1e30f;
            s1[j] = (c <= q0 + r1) ? s1[j] * scale : -1e30f;
            mx0 = fmaxf(mx0, s0[j]);
            mx1 = fmaxf(mx1, s1[j]);
        }
#pragma unroll
        for (int off = 1; off < 8; off <<= 1) {
            mx0 = fmaxf(mx0, __shfl_xor_sync(0xffffffffu, mx0, off));
            mx1 = fmaxf(mx1, __shfl_xor_sync(0xffffffffu, mx1, off));
        }
        const float mn0 = fmaxf(m0, mx0), mn1 = fmaxf(m1, mx1);
        const float c0 = __expf(m0 - mn0), c1 = __expf(m1 - mn1);
        float p0[8], p1[8];
        float ps0 = 0.f, ps1 = 0.f;
#pragma unroll
        for (int j = 0; j < 8; j++) {
            p0[j] = __expf(s0[j] - mn0); ps0 += p0[j];
            p1[j] = __expf(s1[j] - mn1); ps1 += p1[j];
        }
#pragma unroll
        for (int off = 1; off < 8; off <<= 1) {
            ps0 += __shfl_xor_sync(0xffffffffu, ps0, off);
            ps1 += __shfl_xor_sync(0xffffffffu, ps1, off);
        }
        l0 = l0 * c0 + ps0; l1 = l1 * c1 + ps1;
        m0 = mn0; m1 = mn1;
#pragma unroll
        for (int i = 0; i < 16; i++) { acc0[i] *= c0; acc1[i] *= c1; }

#pragma unroll
        for (int j = 0; j < 8; j++) {
#pragma unroll
            for (int kk2 = 0; kk2 < 8; kk2++) {
                const int k   = j * 8 + kk2;
                const int src = (tid & 24) | kk2;
                const float pa = __shfl_sync(0xffffffffu, p0[j], src);
                const float pb = __shfl_sync(0xffffffffu, p1[j], src);
                const float4* vr = (const float4*)&Vs[k * 132 + cg * 16];
#pragma unroll
                for (int i = 0; i < 4; i++) {
                    float4 vv = vr[i];
                    acc0[i * 4 + 0] = fmaf(pa, vv.x, acc0[i * 4 + 0]);
                    acc0[i * 4 + 1] = fmaf(pa, vv.y, acc0[i * 4 + 1]);
                    acc0[i * 4 + 2] = fmaf(pa, vv.z, acc0[i * 4 + 2]);
                    acc0[i * 4 + 3] = fmaf(pa, vv.w, acc0[i * 4 + 3]);
                    acc1[i * 4 + 0] = fmaf(pb, vv.x, acc1[i * 4 + 0]);
                    acc1[i * 4 + 1] = fmaf(pb, vv.y, acc1[i * 4 + 1]);
                    acc1[i * 4 + 2] = fmaf(pb, vv.z, acc1[i * 4 + 2]);
                    acc1[i * 4 + 3] = fmaf(pb, vv.w, acc1[i * 4 + 3]);
                }
            }
        }
    }

    const float il0 = 1.f / l0, il1 = 1.f / l1;
    float* O0 = g_attn + (size_t)(q0 + r0) * D + h * HD + cg * 16;
    float* O1 = g_attn + (size_t)(q0 + r1) * D + h * HD + cg * 16;
#pragma unroll
    for (int i = 0; i < 4; i++) {
        *(float4*)(O0 + i * 4) = make_float4(acc0[i * 4] * il0, acc0[i * 4 + 1] * il0,
                                             acc0[i * 4 + 2] * il0, acc0[i * 4 + 3] * il0);
        *(float4*)(O1 + i * 4) = make_float4(acc1[i * 4] * il1, acc1[i * 4 + 1] * il1,
                                             acc1[i * 4 + 2] * il1, acc1[i * 4 + 3] * il1);
    }
}

// -----------------------------------------------------------------------------
extern "C" void kernel_launch(void* const* d_in, const int* in_sizes, int n_in,
                              void* d_out, int out_size)
{
    const float* x    = (const float*)d_in[0];
    const float* cosb = (const float*)d_in[1];
    const float* sinb = (const float*)d_in[2];
    const float* Wq   = (const float*)d_in[3];
    const float* Wk   = (const float*)d_in[4];
    const float* Wv   = (const float*)d_in[5];
    const float* Wo   = (const float*)d_in[6];
    const float* wq   = (const float*)d_in[7];
    const float* wk   = (const float*)d_in[8];
    const float* wv   = (const float*)d_in[9];
    const float* qnw  = (const float*)d_in[10];
    const float* knw  = (const float*)d_in[11];
    float* out = (float*)d_out;

    float *pq, *pk, *pv, *pattn;
    __nv_bfloat16 *pxh, *pxl, *pwh, *pwl, *pah, *pal;
    cudaGetSymbolAddress((void**)&pq, g_q);
    cudaGetSymbolAddress((void**)&pk, g_k);
    cudaGetSymbolAddress((void**)&pv, g_v);
    cudaGetSymbolAddress((void**)&pattn, g_attn);
    cudaGetSymbolAddress((void**)&pxh, g_xh);
    cudaGetSymbolAddress((void**)&pxl, g_xl);
    cudaGetSymbolAddress((void**)&pwh, g_wh);
    cudaGetSymbolAddress((void**)&pwl, g_wl);
    cudaGetSymbolAddress((void**)&pah, g_ah);
    cudaGetSymbolAddress((void**)&pal, g_al);

    __nv_bfloat16* wh[4];
    __nv_bfloat16* wl[4];
    for (int i = 0; i < 4; i++) { wh[i] = pwh + (size_t)i * D * D; wl[i] = pwl + (size_t)i * D * D; }

    cudaFuncSetAttribute(gemm_bf16s, cudaFuncAttributeMaxDynamicSharedMemorySize, GEMM_SMEM);

    // 0) split x, Wq, Wk, Wv, Wo into bf16 hi/lo
    split_bf16<<<dim3(256, 1, 5), 256>>>(x, pxh, pxl,
                                         Wq, wh[0], wl[0],
                                         Wk, wh[1], wl[1],
                                         Wv, wh[2], wl[2],
                                         Wo, wh[3], wl[3]);

    // 1) QKV projections (mma.sync bf16, 3-pass split)
    gemm_bf16s<<<dim3(16, 16, 3), 256, GEMM_SMEM>>>(pxh, pxl,
                                                    wh[0], wl[0], wh[1], wl[1], wh[2], wl[2],
                                                    pq, pk, pv);

    // 2) conv + SiLU + RMSNorm + RoPE + head transpose
    fuse_post<<<dim3(T, H), HD>>>(cosb, sinb, wq, wk, wv, qnw, knw);

    // 3) causal flash attention (fp32 SIMT)
    const int smem = 3 * 64 * 132 * (int)sizeof(float);
    cudaFuncSetAttribute(flash_attn, cudaFuncAttributeMaxDynamicSharedMemorySize, smem);
    flash_attn<<<dim3(T / 64, H), 256, smem>>>();

    // 4) split attn output, then O-proj -> d_out
    split_bf16<<<dim3(256, 1, 1), 256>>>(pattn, pah, pal,
                                         pattn, pah, pal, pattn, pah, pal,
                                         pattn, pah, pal, pattn, pah, pal);
    gemm_bf16s<<<dim3(16, 16, 1), 256, GEMM_SMEM>>>(pah, pal,
                                                    wh[3], wl[3], wh[3], wl[3], wh[3], wl[3],
                                                    out, out, out);
}

// round 4
// speedup vs baseline: 3.4814x; 2.6218x over previous
#include <cuda_runtime.h>
#include <cuda_bf16.h>
#include <math.h>
#include <stdint.h>

#define T 2048
#define D 2048
#define H 16
#define HD 128
#define RD 64
#define KC 4

// ---------------- scratch (device globals) -----------------------------------
__device__ float g_q[T * D];
__device__ float g_k[T * D];
__device__ float g_v[T * D];

__device__ __nv_bfloat16 g_xh[T * D], g_xl[T * D];
__device__ __nv_bfloat16 g_wh[4][D * D], g_wl[4][D * D];  // Wq,Wk,Wv,Wo
__device__ __nv_bfloat16 g_ah[T * D], g_al[T * D];        // attn out hi/lo

// flash inputs, bf16 hi/lo, [H][T][HD]
__device__ __nv_bfloat16 g_q2h[T * D], g_q2l[T * D];
__device__ __nv_bfloat16 g_k2h[T * D], g_k2l[T * D];
__device__ __nv_bfloat16 g_v2h[T * D], g_v2l[T * D];

// ---------------- PTX helpers --------------------------------------------------
__device__ __forceinline__ uint32_t smem_u32(const void* p) {
    uint32_t a;
    asm("{ .reg .u64 t; cvta.to.shared.u64 t, %1; cvt.u32.u64 %0, t; }" : "=r"(a) : "l"(p));
    return a;
}

#define CP16(dst, src) \
    asm volatile("cp.async.cg.shared.global [%0], [%1], 16;" :: "r"(dst), "l"(src))
#define CP_COMMIT() asm volatile("cp.async.commit_group;" ::: "memory")
#define CP_WAIT(n)  asm volatile("cp.async.wait_group %0;" :: "n"(n) : "memory")

#define LDSM4(r0, r1, r2, r3, addr)                                      \
    asm volatile("ldmatrix.sync.aligned.m8n8.x4.shared.b16 {%0,%1,%2,%3}, [%4];" \
        : "=r"(r0), "=r"(r1), "=r"(r2), "=r"(r3) : "r"(addr))

#define LDSM4T(r0, r1, r2, r3, addr)                                     \
    asm volatile("ldmatrix.sync.aligned.m8n8.x4.trans.shared.b16 {%0,%1,%2,%3}, [%4];" \
        : "=r"(r0), "=r"(r1), "=r"(r2), "=r"(r3) : "r"(addr))

#define MMA16816(d, a, b)                                                \
    asm volatile("mma.sync.aligned.m16n8k16.row.col.f32.bf16.bf16.f32 "  \
        "{%0,%1,%2,%3}, {%4,%5,%6,%7}, {%8,%9}, {%0,%1,%2,%3};"          \
        : "+f"((d)[0]), "+f"((d)[1]), "+f"((d)[2]), "+f"((d)[3])         \
        : "r"((a)[0]), "r"((a)[1]), "r"((a)[2]), "r"((a)[3]),            \
          "r"((b)[0]), "r"((b)[1]))

__device__ __forceinline__ void split2(float a, float b, uint32_t& hi, uint32_t& lo) {
    __nv_bfloat162 h = __floats2bfloat162_rn(a, b);
    __nv_bfloat162 l = __floats2bfloat162_rn(a - __low2float(h), b - __high2float(h));
    hi = *(uint32_t*)&h;
    lo = *(uint32_t*)&l;
}

// ---------------- fp32 -> bf16 hi/lo split (inputs) ----------------------------
__global__ void split_bf16(const float* __restrict__ s0, __nv_bfloat16* h0, __nv_bfloat16* l0,
                           const float* __restrict__ s1, __nv_bfloat16* h1, __nv_bfloat16* l1,
                           const float* __restrict__ s2, __nv_bfloat16* h2, __nv_bfloat16* l2,
                           const float* __restrict__ s3, __nv_bfloat16* h3, __nv_bfloat16* l3,
                           const float* __restrict__ s4, __nv_bfloat16* h4, __nv_bfloat16* l4)
{
    const float* s; __nv_bfloat16 *h, *l;
    switch (blockIdx.z) {
        case 0:  s = s0; h = h0; l = l0; break;
        case 1:  s = s1; h = h1; l = l1; break;
        case 2:  s = s2; h = h2; l = l2; break;
        case 3:  s = s3; h = h3; l = l3; break;
        default: s = s4; h = h4; l = l4; break;
    }
    const int n4 = T * D / 4;
    for (int i = blockIdx.x * blockDim.x + threadIdx.x; i < n4; i += gridDim.x * blockDim.x) {
        float4 v = ((const float4*)s)[i];
        __nv_bfloat162 h01 = __floats2bfloat162_rn(v.x, v.y);
        __nv_bfloat162 h23 = __floats2bfloat162_rn(v.z, v.w);
        __nv_bfloat162 l01 = __floats2bfloat162_rn(v.x - __low2float(h01), v.y - __high2float(h01));
        __nv_bfloat162 l23 = __floats2bfloat162_rn(v.z - __low2float(h23), v.w - __high2float(h23));
        ((__nv_bfloat162*)h)[2 * i]     = h01;
        ((__nv_bfloat162*)h)[2 * i + 1] = h23;
        ((__nv_bfloat162*)l)[2 * i]     = l01;
        ((__nv_bfloat162*)l)[2 * i + 1] = l23;
    }
}

// ---------------- bf16-split GEMM (NT), unchanged from R3 ----------------------
#define BK      32
#define NCK     (D / BK)
#define SROW    40
#define TILE_E  (128 * SROW)
#define STAGE_E (4 * TILE_E)
#define GEMM_SMEM (3 * STAGE_E * 2)

__global__ __launch_bounds__(256, 1)
void gemm_bf16s(const __nv_bfloat16* __restrict__ Ah_, const __nv_bfloat16* __restrict__ Al_,
                const __nv_bfloat16* __restrict__ Bh0, const __nv_bfloat16* __restrict__ Bl0,
                const __nv_bfloat16* __restrict__ Bh1, const __nv_bfloat16* __restrict__ Bl1,
                const __nv_bfloat16* __restrict__ Bh2, const __nv_bfloat16* __restrict__ Bl2,
                float* __restrict__ C0, float* __restrict__ C1, float* __restrict__ C2)
{
    const __nv_bfloat16* Bh_ = (blockIdx.z == 0) ? Bh0 : ((blockIdx.z == 1) ? Bh1 : Bh2);
    const __nv_bfloat16* Bl_ = (blockIdx.z == 0) ? Bl0 : ((blockIdx.z == 1) ? Bl1 : Bl2);
    float*               C   = (blockIdx.z == 0) ? C0  : ((blockIdx.z == 1) ? C1  : C2);

    extern __shared__ __nv_bfloat16 sm[];
    const uint32_t sbase = smem_u32(sm);

    const int tid  = threadIdx.x;
    const int lane = tid & 31;
    const int warp = tid >> 5;
    const int wm0  = (warp & 3) * 32;
    const int wn0  = (warp >> 2) * 64;
    const int brow = blockIdx.y * 128;
    const int bcol = blockIdx.x * 128;

    const int rld = tid >> 2;
    const int cld = tid & 3;

    auto load_chunk = [&](int c, int slot) {
        const int k0 = c * BK;
        const uint32_t s0 = sbase + (uint32_t)slot * (STAGE_E * 2);
#pragma unroll
        for (int t = 0; t < 2; t++) {
            const int r = rld + t * 64;
            const uint32_t so = s0 + 2 * (r * SROW + cld * 8);
            const size_t ga = (size_t)(brow + r) * D + k0 + cld * 8;
            const size_t gb = (size_t)(bcol + r) * D + k0 + cld * 8;
            CP16(so,              Ah_ + ga);
            CP16(so + 2 * TILE_E, Al_ + ga);
            CP16(so + 4 * TILE_E, Bh_ + gb);
            CP16(so + 6 * TILE_E, Bl_ + gb);
        }
    };

    float acc[2][8][4];
#pragma unroll
    for (int mt = 0; mt < 2; mt++)
#pragma unroll
        for (int nt = 0; nt < 8; nt++)
#pragma unroll
            for (int i = 0; i < 4; i++) acc[mt][nt][i] = 0.f;

    load_chunk(0, 0); CP_COMMIT();
    load_chunk(1, 1); CP_COMMIT();

    const int arow = wm0 + (lane & 15);
    const int akof = (lane >> 4) << 3;
    const int nrow = wn0 + (lane & 7) + ((lane & 16) >> 1);
    const int bkof = lane & 8;

    for (int c = 0; c < NCK; c++) {
        CP_WAIT(1);
        __syncthreads();
        if (c + 2 < NCK) load_chunk(c + 2, (c + 2) % 3);
        CP_COMMIT();

        const uint32_t sb = sbase + (uint32_t)(c % 3) * (STAGE_E * 2);
#pragma unroll
        for (int ks = 0; ks < 2; ks++) {
            const int kb = ks << 4;
            uint32_t ah[2][4], al[2][4], bh[8][2], bl[8][2];
#pragma unroll
            for (int mt = 0; mt < 2; mt++) {
                const uint32_t ad = sb + 2 * ((arow + mt * 16) * SROW + kb + akof);
                LDSM4(ah[mt][0], ah[mt][1], ah[mt][2], ah[mt][3], ad);
                LDSM4(al[mt][0], al[mt][1], al[mt][2], al[mt][3], ad + 2 * TILE_E);
            }
#pragma unroll
            for (int np = 0; np < 4; np++) {
                const uint32_t bd = sb + 2 * (2 * TILE_E + (nrow + np * 16) * SROW + kb + bkof);
                LDSM4(bh[2 * np][0], bh[2 * np][1], bh[2 * np + 1][0], bh[2 * np + 1][1], bd);
                LDSM4(bl[2 * np][0], bl[2 * np][1], bl[2 * np + 1][0], bl[2 * np + 1][1],
                      bd + 2 * TILE_E);
            }
#pragma unroll
            for (int mt = 0; mt < 2; mt++)
#pragma unroll
                for (int nt = 0; nt < 8; nt++) {
                    MMA16816(acc[mt][nt], ah[mt], bh[nt]);
                    MMA16816(acc[mt][nt], ah[mt], bl[nt]);
                    MMA16816(acc[mt][nt], al[mt], bh[nt]);
                }
        }
    }

#pragma unroll
    for (int mt = 0; mt < 2; mt++) {
        const int row = brow + wm0 + mt * 16 + (lane >> 2);
#pragma unroll
        for (int nt = 0; nt < 8; nt++) {
            const int col = bcol + wn0 + nt * 8 + 2 * (lane & 3);
            float* p = C + (size_t)row * D + col;
            p[0] = acc[mt][nt][0];
            p[1] = acc[mt][nt][1];
            p += 8 * (size_t)D;
            p[0] = acc[mt][nt][2];
            p[1] = acc[mt][nt][3];
        }
    }
}

// -------- fused: conv+SiLU, RMSNorm, RoPE, transpose; emits bf16 hi/lo ---------
__global__ void fuse_post(const float* __restrict__ cosb,
                          const float* __restrict__ sinb,
                          const float* __restrict__ wq,
                          const float* __restrict__ wk,
                          const float* __restrict__ wv,
                          const float* __restrict__ qnw,
                          const float* __restrict__ knw)
{
    const int t  = blockIdx.x;
    const int h  = blockIdx.y;
    const int hd = threadIdx.x;
    const int d  = h * HD + hd;

    float yq = 0.f, yk = 0.f, yv = 0.f;
#pragma unroll
    for (int j = 0; j < KC; j++) {
        int tt = t - (KC - 1) + j;
        if (tt >= 0) {
            size_t o = (size_t)tt * D + d;
            yq = fmaf(g_q[o], wq[d * KC + j], yq);
            yk = fmaf(g_k[o], wk[d * KC + j], yk);
            yv = fmaf(g_v[o], wv[d * KC + j], yv);
        }
    }
    yq = yq / (1.f + __expf(-yq));
    yk = yk / (1.f + __expf(-yk));
    yv = yv / (1.f + __expf(-yv));

    float vq = yq * yq, vk = yk * yk;
#pragma unroll
    for (int off = 16; off > 0; off >>= 1) {
        vq += __shfl_xor_sync(0xffffffffu, vq, off);
        vk += __shfl_xor_sync(0xffffffffu, vk, off);
    }
    __shared__ float rq[4], rk[4], sq[HD], sk[HD];
    const int w = hd >> 5;
    if ((hd & 31) == 0) { rq[w] = vq; rk[w] = vk; }
    __syncthreads();
    const float varq = (rq[0] + rq[1] + rq[2] + rq[3]) * (1.f / HD);
    const float vark = (rk[0] + rk[1] + rk[2] + rk[3]) * (1.f / HD);
    sq[hd] = yq * rsqrtf(varq + 1e-5f) * qnw[hd];
    sk[hd] = yk * rsqrtf(vark + 1e-5f) * knw[hd];
    __syncthreads();

    float oq, ok;
    if (hd < RD) {
        const float cs = cosb[t * RD + hd];
        const float sn = sinb[t * RD + hd];
        const float rqv = (hd < RD / 2) ? -sq[hd + RD / 2] : sq[hd - RD / 2];
        const float rkv = (hd < RD / 2) ? -sk[hd + RD / 2] : sk[hd - RD / 2];
        oq = -(sq[hd] * cs + rqv * sn);
        ok = -(sk[hd] * cs + rkv * sn);
    } else {
        oq = sq[hd];
        ok = sk[hd];
    }

    const float scale = 0.08838834764831845f;  // 1/sqrt(128), folded into q
    oq *= scale;

    const size_t o = ((size_t)h * T + t) * HD + hd;
    __nv_bfloat16 b;
    b = __float2bfloat16(oq); g_q2h[o] = b; g_q2l[o] = __float2bfloat16(oq - __bfloat162float(b));
    b = __float2bfloat16(ok); g_k2h[o] = b; g_k2l[o] = __float2bfloat16(ok - __bfloat162float(b));
    b = __float2bfloat16(yv); g_v2h[o] = b; g_v2l[o] = __float2bfloat16(yv - __bfloat162float(b));
}

// ---------------- flash attention via mma.sync bf16 3-pass split ---------------
// 64x64 tiles. 8 warps: wm=wid&3 (16 q rows each), wn=wid>>2 (32 kv cols each).
// Each warp accumulates partial O (16 rows x 128 HD) over its kv slice;
// pairs combine in smem at the end. Double-buffered cp.async K/V.
#define FSTR  136
#define FTSZ  (64 * FSTR)                 // elems per tile array
#define FSMEM (10 * FTSZ * 2)             // Qh,Ql + 2 stages x (Kh,Kl,Vh,Vl)

__global__ __launch_bounds__(256, 1)
void flash_mma()
{
    extern __shared__ __nv_bfloat16 fsm[];
    __shared__ float red_m[2][64], red_s[2][64];

    const int tid  = threadIdx.x;
    const int lane = tid & 31;
    const int wid  = tid >> 5;
    const int wm   = wid & 3;
    const int wn   = wid >> 2;
    const int h    = blockIdx.y;
    const int qt   = gridDim.x - 1 - blockIdx.x;  // heavy tiles first
    const int q0   = qt * 64;

    const uint32_t sb  = smem_u32(fsm);
    const uint32_t sQh = sb;                       // +FTSZ*2 -> Ql

    auto ldq = [&]() {
#pragma unroll
        for (int t = 0; t < 4; t++) {
            const int idx = t * 256 + tid;
            const int r   = idx >> 4;
            const int cc  = idx & 15;
            const uint32_t so = 2 * (r * FSTR + cc * 8);
            const size_t  go = ((size_t)h * T + q0 + r) * HD + cc * 8;
            CP16(sQh + so,            g_q2h + go);
            CP16(sQh + FTSZ * 2 + so, g_q2l + go);
        }
    };
    auto ldkv = [&](int kt2, int s) {
        const uint32_t kb = sb + (uint32_t)(2 + 4 * s) * (FTSZ * 2);
#pragma unroll
        for (int t = 0; t < 4; t++) {
            const int idx = t * 256 + tid;
            const int r   = idx >> 4;
            const int cc  = idx & 15;
            const uint32_t so = 2 * (r * FSTR + cc * 8);
            const size_t  go = ((size_t)h * T + kt2 * 64 + r) * HD + cc * 8;
            CP16(kb + so,                g_k2h + go);
            CP16(kb + FTSZ * 2 + so,     g_k2l + go);
            CP16(kb + 2 * FTSZ * 2 + so, g_v2h + go);
            CP16(kb + 3 * FTSZ * 2 + so, g_v2l + go);
        }
    };

    float acco[16][4];
#pragma unroll
    for (int nt = 0; nt < 16; nt++)
#pragma unroll
        for (int i = 0; i < 4; i++) acco[nt][i] = 0.f;
    float m0 = -1e30f, m1 = -1e30f, l0 = 0.f, l1 = 0.f;

    ldq(); ldkv(0, 0); CP_COMMIT();
    if (qt >= 1) ldkv(1, 1);
    CP_COMMIT();

    const int r0l = wm * 16 + (lane >> 2);  // local q row (0..63)
    const int r1l = r0l + 8;
    const uint32_t qoff = 2 * ((wm * 16 + (lane & 15)) * FSTR + ((lane >> 4) << 3));
    const int krow = (lane & 7) + ((lane & 16) >> 1);

    for (int kt = 0; kt <= qt; kt++) {
        CP_WAIT(1);
        __syncthreads();
        const uint32_t kb = sb + (uint32_t)(2 + 4 * (kt & 1)) * (FTSZ * 2);

        // ---- S = Q K^T (3-pass) ----
        float accs[4][4];
#pragma unroll
        for (int nt = 0; nt < 4; nt++)
#pragma unroll
            for (int i = 0; i < 4; i++) accs[nt][i] = 0.f;

#pragma unroll
        for (int j = 0; j < 8; j++) {
            uint32_t ah[4], al[4];
            const uint32_t qa = sQh + qoff + 2 * (j * 16);
            LDSM4(ah[0], ah[1], ah[2], ah[3], qa);
            LDSM4(al[0], al[1], al[2], al[3], qa + FTSZ * 2);
            uint32_t bh[4][2], bl[4][2];
#pragma unroll
            for (int np = 0; np < 2; np++) {
                const uint32_t ka = kb + 2 * ((wn * 32 + np * 16 + krow) * FSTR + j * 16 + (lane & 8));
                LDSM4(bh[2 * np][0], bh[2 * np][1], bh[2 * np + 1][0], bh[2 * np + 1][1], ka);
                LDSM4(bl[2 * np][0], bl[2 * np][1], bl[2 * np + 1][0], bl[2 * np + 1][1],
                      ka + FTSZ * 2);
            }
#pragma unroll
            for (int nt = 0; nt < 4; nt++) {
                MMA16816(accs[nt], ah, bh[nt]);
                MMA16816(accs[nt], ah, bl[nt]);
                MMA16816(accs[nt], al, bh[nt]);
            }
        }

        // ---- causal mask (diagonal tile only) ----
        if (kt == qt) {
#pragma unroll
            for (int nt = 0; nt < 4; nt++) {
                const int c0 = wn * 32 + nt * 8 + 2 * (lane & 3);
                if (c0     > r0l) accs[nt][0] = -1e30f;
                if (c0 + 1 > r0l) accs[nt][1] = -1e30f;
                if (c0     > r1l) accs[nt][2] = -1e30f;
                if (c0 + 1 > r1l) accs[nt][3] = -1e30f;
            }
        }

        // ---- row max (intra-warp + cross-warp via smem) ----
        float mx0 = -1e30f, mx1 = -1e30f;
#pragma unroll
        for (int nt = 0; nt < 4; nt++) {
            mx0 = fmaxf(mx0, fmaxf(accs[nt][0], accs[nt][1]));
            mx1 = fmaxf(mx1, fmaxf(accs[nt][2], accs[nt][3]));
        }
        mx0 = fmaxf(mx0, __shfl_xor_sync(0xffffffffu, mx0, 1));
        mx0 = fmaxf(mx0, __shfl_xor_sync(0xffffffffu, mx0, 2));
        mx1 = fmaxf(mx1, __shfl_xor_sync(0xffffffffu, mx1, 1));
        mx1 = fmaxf(mx1, __shfl_xor_sync(0xffffffffu, mx1, 2));
        if ((lane & 3) == 0) { red_m[wn][r0l] = mx0; red_m[wn][r1l] = mx1; }
        __syncthreads();
        const float tm0 = fmaxf(red_m[0][r0l], red_m[1][r0l]);
        const float tm1 = fmaxf(red_m[0][r1l], red_m[1][r1l]);
        const float mn0 = fmaxf(m0, tm0), mn1 = fmaxf(m1, tm1);
        const float c0 = __expf(m0 - mn0), c1 = __expf(m1 - mn1);

        // ---- p = exp(s - m), row sums ----
        float p[4][4];
        float ps0 = 0.f, ps1 = 0.f;
#pragma unroll
        for (int nt = 0; nt < 4; nt++) {
            p[nt][0] = __expf(accs[nt][0] - mn0); ps0 += p[nt][0];
            p[nt][1] = __expf(accs[nt][1] - mn0); ps0 += p[nt][1];
            p[nt][2] = __expf(accs[nt][2] - mn1); ps1 += p[nt][2];
            p[nt][3] = __expf(accs[nt][3] - mn1); ps1 += p[nt][3];
        }
        ps0 += __shfl_xor_sync(0xffffffffu, ps0, 1);
        ps0 += __shfl_xor_sync(0xffffffffu, ps0, 2);
        ps1 += __shfl_xor_sync(0xffffffffu, ps1, 1);
        ps1 += __shfl_xor_sync(0xffffffffu, ps1, 2);
        if ((lane & 3) == 0) { red_s[wn][r0l] = ps0; red_s[wn][r1l] = ps1; }
        __syncthreads();
        l0 = l0 * c0 + red_s[0][r0l] + red_s[1][r0l];
        l1 = l1 * c1 + red_s[0][r1l] + red_s[1][r1l];
        m0 = mn0; m1 = mn1;

#pragma unroll
        for (int nt = 0; nt < 16; nt++) {
            acco[nt][0] *= c0; acco[nt][1] *= c0;
            acco[nt][2] *= c1; acco[nt][3] *= c1;
        }

        // ---- P hi/lo A-fragments (acc layout == A layout) ----
        uint32_t pha[2][4], pla[2][4];
#pragma unroll
        for (int j = 0; j < 2; j++) {
            split2(p[2 * j][0],     p[2 * j][1],     pha[j][0], pla[j][0]);
            split2(p[2 * j][2],     p[2 * j][3],     pha[j][1], pla[j][1]);
            split2(p[2 * j + 1][0], p[2 * j + 1][1], pha[j][2], pla[j][2]);
            split2(p[2 * j + 1][2], p[2 * j + 1][3], pha[j][3], pla[j][3]);
        }

        // ---- O += P V (3-pass), V via ldmatrix.trans ----
        const uint32_t vb = kb + 2 * (2 * FTSZ);
#pragma unroll
        for (int j = 0; j < 2; j++) {
            const int k0 = wn * 32 + j * 16 + (lane & 15);
#pragma unroll
            for (int np = 0; np < 8; np++) {
                const uint32_t va = vb + 2 * (k0 * FSTR + np * 16 + ((lane >> 4) << 3));
                uint32_t vh[4], vl[4];
                LDSM4T(vh[0], vh[1], vh[2], vh[3], va);
                LDSM4T(vl[0], vl[1], vl[2], vl[3], va + FTSZ * 2);
                MMA16816(acco[2 * np],     pha[j], vh);
                MMA16816(acco[2 * np],     pha[j], vl);
                MMA16816(acco[2 * np],     pla[j], vh);
                MMA16816(acco[2 * np + 1], pha[j], vh + 2);
                MMA16816(acco[2 * np + 1], pha[j], vl + 2);
                MMA16816(acco[2 * np + 1], pla[j], vh + 2);
            }
        }

        __syncthreads();
        if (kt + 2 <= qt) ldkv(kt + 2, kt & 1);
        CP_COMMIT();
    }

    // ---- combine warp pairs, normalize, emit bf16 hi/lo ----
    const float il0 = 1.f / l0, il1 = 1.f / l1;
    float* os = (float*)fsm;  // 64 x 132, overlaps Q (done with it)
    __syncthreads();
    if (wn == 1) {
#pragma unroll
        for (int nt = 0; nt < 16; nt++) {
            const int col = nt * 8 + 2 * (lane & 3);
            os[r0l * 132 + col]     = acco[nt][0];
            os[r0l * 132 + col + 1] = acco[nt][1];
            os[r1l * 132 + col]     = acco[nt][2];
            os[r1l * 132 + col + 1] = acco[nt][3];
        }
    }
    __syncthreads();
    if (wn == 0) {
#pragma unroll
        for (int nt = 0; nt < 16; nt++) {
            const int col = nt * 8 + 2 * (lane & 3);
            const float v0 = (acco[nt][0] + os[r0l * 132 + col])     * il0;
            const float v1 = (acco[nt][1] + os[r0l * 132 + col + 1]) * il0;
            const float v2 = (acco[nt][2] + os[r1l * 132 + col])     * il1;
            const float v3 = (acco[nt][3] + os[r1l * 132 + col + 1]) * il1;
            uint32_t hi, lo;
            const size_t o0 = (size_t)(q0 + r0l) * D + h * HD + col;
            const size_t o1 = (size_t)(q0 + r1l) * D + h * HD + col;
            split2(v0, v1, hi, lo);
            *(uint32_t*)&g_ah[o0] = hi; *(uint32_t*)&g_al[o0] = lo;
            split2(v2, v3, hi, lo);
            *(uint32_t*)&g_ah[o1] = hi; *(uint32_t*)&g_al[o1] = lo;
        }
    }
}

// -----------------------------------------------------------------------------
extern "C" void kernel_launch(void* const* d_in, const int* in_sizes, int n_in,
                              void* d_out, int out_size)
{
    const float* x    = (const float*)d_in[0];
    const float* cosb = (const float*)d_in[1];
    const float* sinb = (const float*)d_in[2];
    const float* Wq   = (const float*)d_in[3];
    const float* Wk   = (const float*)d_in[4];
    const float* Wv   = (const float*)d_in[5];
    const float* Wo   = (const float*)d_in[6];
    const float* wq   = (const float*)d_in[7];
    const float* wk   = (const float*)d_in[8];
    const float* wv   = (const float*)d_in[9];
    const float* qnw  = (const float*)d_in[10];
    const float* knw  = (const float*)d_in[11];
    float* out = (float*)d_out;

    float *pq, *pk, *pv;
    __nv_bfloat16 *pxh, *pxl, *pwh, *pwl, *pah, *pal;
    cudaGetSymbolAddress((void**)&pq, g_q);
    cudaGetSymbolAddress((void**)&pk, g_k);
    cudaGetSymbolAddress((void**)&pv, g_v);
    cudaGetSymbolAddress((void**)&pxh, g_xh);
    cudaGetSymbolAddress((void**)&pxl, g_xl);
    cudaGetSymbolAddress((void**)&pwh, g_wh);
    cudaGetSymbolAddress((void**)&pwl, g_wl);
    cudaGetSymbolAddress((void**)&pah, g_ah);
    cudaGetSymbolAddress((void**)&pal, g_al);

    __nv_bfloat16* wh[4];
    __nv_bfloat16* wl[4];
    for (int i = 0; i < 4; i++) { wh[i] = pwh + (size_t)i * D * D; wl[i] = pwl + (size_t)i * D * D; }

    cudaFuncSetAttribute(gemm_bf16s, cudaFuncAttributeMaxDynamicSharedMemorySize, GEMM_SMEM);
    cudaFuncSetAttribute(flash_mma,  cudaFuncAttributeMaxDynamicSharedMemorySize, FSMEM);

    // 0) split x, Wq, Wk, Wv, Wo into bf16 hi/lo
    split_bf16<<<dim3(256, 1, 5), 256>>>(x, pxh, pxl,
                                         Wq, wh[0], wl[0],
                                         Wk, wh[1], wl[1],
                                         Wv, wh[2], wl[2],
                                         Wo, wh[3], wl[3]);

    // 1) QKV projections
    gemm_bf16s<<<dim3(16, 16, 3), 256, GEMM_SMEM>>>(pxh, pxl,
                                                    wh[0], wl[0], wh[1], wl[1], wh[2], wl[2],
                                                    pq, pk, pv);

    // 2) conv + SiLU + RMSNorm + RoPE + transpose (emits bf16 hi/lo, q scaled)
    fuse_post<<<dim3(T, H), HD>>>(cosb, sinb, wq, wk, wv, qnw, knw);

    // 3) causal flash attention (tensor cores, 3-pass split)
    flash_mma<<<dim3(T / 64, H), 256, FSMEM>>>();

    // 4) O-proj -> d_out (reads bf16 hi/lo attn directly)
    gemm_bf16s<<<dim3(16, 16, 1), 256, GEMM_SMEM>>>(pah, pal,
                                                    wh[3], wl[3], wh[3], wl[3], wh[3], wl[3],
                                                    out, out, out);
}

// round 6
// speedup vs baseline: 3.6559x; 1.0501x over previous
#include <cuda_runtime.h>
#include <cuda_bf16.h>
#include <math.h>
#include <stdint.h>

#define T 2048
#define D 2048
#define H 16
#define HD 128
#define RD 64
#define KC 4

// ---------------- scratch (device globals) -----------------------------------
__device__ float g_q[T * D];
__device__ float g_k[T * D];
__device__ float g_v[T * D];

__device__ __nv_bfloat16 g_xh[T * D], g_xl[T * D];
__device__ __nv_bfloat16 g_wh[4][D * D], g_wl[4][D * D];  // Wq,Wk,Wv,Wo
__device__ __nv_bfloat16 g_ah[T * D], g_al[T * D];        // attn out hi/lo

// flash inputs, bf16 hi/lo, [H][T][HD]
__device__ __nv_bfloat16 g_q2h[T * D], g_q2l[T * D];
__device__ __nv_bfloat16 g_k2h[T * D], g_k2l[T * D];
__device__ __nv_bfloat16 g_v2h[T * D], g_v2l[T * D];

// ---------------- PTX helpers --------------------------------------------------
__device__ __forceinline__ uint32_t smem_u32(const void* p) {
    uint32_t a;
    asm("{ .reg .u64 t; cvta.to.shared.u64 t, %1; cvt.u32.u64 %0, t; }" : "=r"(a) : "l"(p));
    return a;
}

#define CP16(dst, src) \
    asm volatile("cp.async.cg.shared.global [%0], [%1], 16;" :: "r"(dst), "l"(src))
#define CP_COMMIT() asm volatile("cp.async.commit_group;" ::: "memory")
#define CP_WAIT(n)  asm volatile("cp.async.wait_group %0;" :: "n"(n) : "memory")

#define LDSM4(r0, r1, r2, r3, addr)                                      \
    asm volatile("ldmatrix.sync.aligned.m8n8.x4.shared.b16 {%0,%1,%2,%3}, [%4];" \
        : "=r"(r0), "=r"(r1), "=r"(r2), "=r"(r3) : "r"(addr))

#define LDSM4T(r0, r1, r2, r3, addr)                                     \
    asm volatile("ldmatrix.sync.aligned.m8n8.x4.trans.shared.b16 {%0,%1,%2,%3}, [%4];" \
        : "=r"(r0), "=r"(r1), "=r"(r2), "=r"(r3) : "r"(addr))

#define MMA16816(d, a, b)                                                \
    asm volatile("mma.sync.aligned.m16n8k16.row.col.f32.bf16.bf16.f32 "  \
        "{%0,%1,%2,%3}, {%4,%5,%6,%7}, {%8,%9}, {%0,%1,%2,%3};"          \
        : "+f"((d)[0]), "+f"((d)[1]), "+f"((d)[2]), "+f"((d)[3])         \
        : "r"((a)[0]), "r"((a)[1]), "r"((a)[2]), "r"((a)[3]),            \
          "r"((b)[0]), "r"((b)[1]))

__device__ __forceinline__ void split2(float a, float b, uint32_t& hi, uint32_t& lo) {
    __nv_bfloat162 h = __floats2bfloat162_rn(a, b);
    __nv_bfloat162 l = __floats2bfloat162_rn(a - __low2float(h), b - __high2float(h));
    hi = *(uint32_t*)&h;
    lo = *(uint32_t*)&l;
}

// ---------------- fp32 -> bf16 hi/lo split (inputs) ----------------------------
__global__ void split_bf16(const float* __restrict__ s0, __nv_bfloat16* h0, __nv_bfloat16* l0,
                           const float* __restrict__ s1, __nv_bfloat16* h1, __nv_bfloat16* l1,
                           const float* __restrict__ s2, __nv_bfloat16* h2, __nv_bfloat16* l2,
                           const float* __restrict__ s3, __nv_bfloat16* h3, __nv_bfloat16* l3,
                           const float* __restrict__ s4, __nv_bfloat16* h4, __nv_bfloat16* l4)
{
    const float* s; __nv_bfloat16 *h, *l;
    switch (blockIdx.z) {
        case 0:  s = s0; h = h0; l = l0; break;
        case 1:  s = s1; h = h1; l = l1; break;
        case 2:  s = s2; h = h2; l = l2; break;
        case 3:  s = s3; h = h3; l = l3; break;
        default: s = s4; h = h4; l = l4; break;
    }
    const int n4 = T * D / 4;
    for (int i = blockIdx.x * blockDim.x + threadIdx.x; i < n4; i += gridDim.x * blockDim.x) {
        float4 v = ((const float4*)s)[i];
        __nv_bfloat162 h01 = __floats2bfloat162_rn(v.x, v.y);
        __nv_bfloat162 h23 = __floats2bfloat162_rn(v.z, v.w);
        __nv_bfloat162 l01 = __floats2bfloat162_rn(v.x - __low2float(h01), v.y - __high2float(h01));
        __nv_bfloat162 l23 = __floats2bfloat162_rn(v.z - __low2float(h23), v.w - __high2float(h23));
        ((__nv_bfloat162*)h)[2 * i]     = h01;
        ((__nv_bfloat162*)h)[2 * i + 1] = h23;
        ((__nv_bfloat162*)l)[2 * i]     = l01;
        ((__nv_bfloat162*)l)[2 * i + 1] = l23;
    }
}

// ---------------- bf16-split GEMM (NT), 2-stage, 2 CTA/SM ---------------------
#define BK      32
#define NCK     (D / BK)
#define SROW    40
#define TILE_E  (128 * SROW)
#define STAGE_E (4 * TILE_E)
#define GEMM_SMEM (2 * STAGE_E * 2)   // 81920 bytes -> 2 CTAs/SM

__global__ __launch_bounds__(256, 2)
void gemm_bf16s(const __nv_bfloat16* __restrict__ Ah_, const __nv_bfloat16* __restrict__ Al_,
                const __nv_bfloat16* __restrict__ Bh0, const __nv_bfloat16* __restrict__ Bl0,
                const __nv_bfloat16* __restrict__ Bh1, const __nv_bfloat16* __restrict__ Bl1,
                const __nv_bfloat16* __restrict__ Bh2, const __nv_bfloat16* __restrict__ Bl2,
                float* __restrict__ C0, float* __restrict__ C1, float* __restrict__ C2)
{
    const __nv_bfloat16* Bh_ = (blockIdx.z == 0) ? Bh0 : ((blockIdx.z == 1) ? Bh1 : Bh2);
    const __nv_bfloat16* Bl_ = (blockIdx.z == 0) ? Bl0 : ((blockIdx.z == 1) ? Bl1 : Bl2);
    float*               C   = (blockIdx.z == 0) ? C0  : ((blockIdx.z == 1) ? C1  : C2);

    extern __shared__ __nv_bfloat16 sm[];
    const uint32_t sbase = smem_u32(sm);

    const int tid  = threadIdx.x;
    const int lane = tid & 31;
    const int warp = tid >> 5;
    const int wm0  = (warp & 3) * 32;
    const int wn0  = (warp >> 2) * 64;
    const int brow = blockIdx.y * 128;
    const int bcol = blockIdx.x * 128;

    const int rld = tid >> 2;
    const int cld = tid & 3;

    auto load_chunk = [&](int c, int slot) {
        const int k0 = c * BK;
        const uint32_t s0 = sbase + (uint32_t)slot * (STAGE_E * 2);
#pragma unroll
        for (int t = 0; t < 2; t++) {
            const int r = rld + t * 64;
            const uint32_t so = s0 + 2 * (r * SROW + cld * 8);
            const size_t ga = (size_t)(brow + r) * D + k0 + cld * 8;
            const size_t gb = (size_t)(bcol + r) * D + k0 + cld * 8;
            CP16(so,              Ah_ + ga);
            CP16(so + 2 * TILE_E, Al_ + ga);
            CP16(so + 4 * TILE_E, Bh_ + gb);
            CP16(so + 6 * TILE_E, Bl_ + gb);
        }
    };

    float acc[2][8][4];
#pragma unroll
    for (int mt = 0; mt < 2; mt++)
#pragma unroll
        for (int nt = 0; nt < 8; nt++)
#pragma unroll
            for (int i = 0; i < 4; i++) acc[mt][nt][i] = 0.f;

    load_chunk(0, 0); CP_COMMIT();
    load_chunk(1, 1); CP_COMMIT();

    const int arow = wm0 + (lane & 15);
    const int akof = (lane >> 4) << 3;
    const int nrow = wn0 + (lane & 7) + ((lane & 16) >> 1);
    const int bkof = lane & 8;

    for (int c = 0; c < NCK; c++) {
        CP_WAIT(1);
        __syncthreads();

        const uint32_t sb = sbase + (uint32_t)(c & 1) * (STAGE_E * 2);
#pragma unroll
        for (int ks = 0; ks < 2; ks++) {
            const int kb = ks << 4;
            uint32_t ah[2][4], al[2][4], bh[8][2], bl[8][2];
#pragma unroll
            for (int mt = 0; mt < 2; mt++) {
                const uint32_t ad = sb + 2 * ((arow + mt * 16) * SROW + kb + akof);
                LDSM4(ah[mt][0], ah[mt][1], ah[mt][2], ah[mt][3], ad);
                LDSM4(al[mt][0], al[mt][1], al[mt][2], al[mt][3], ad + 2 * TILE_E);
            }
#pragma unroll
            for (int np = 0; np < 4; np++) {
                const uint32_t bd = sb + 2 * (2 * TILE_E + (nrow + np * 16) * SROW + kb + bkof);
                LDSM4(bh[2 * np][0], bh[2 * np][1], bh[2 * np + 1][0], bh[2 * np + 1][1], bd);
                LDSM4(bl[2 * np][0], bl[2 * np][1], bl[2 * np + 1][0], bl[2 * np + 1][1],
                      bd + 2 * TILE_E);
            }
#pragma unroll
            for (int mt = 0; mt < 2; mt++)
#pragma unroll
                for (int nt = 0; nt < 8; nt++) {
                    MMA16816(acc[mt][nt], ah[mt], bh[nt]);
                    MMA16816(acc[mt][nt], ah[mt], bl[nt]);
                    MMA16816(acc[mt][nt], al[mt], bh[nt]);
                }
        }

        __syncthreads();
        if (c + 2 < NCK) load_chunk(c + 2, c & 1);
        CP_COMMIT();
    }

#pragma unroll
    for (int mt = 0; mt < 2; mt++) {
        const int row = brow + wm0 + mt * 16 + (lane >> 2);
#pragma unroll
        for (int nt = 0; nt < 8; nt++) {
            const int col = bcol + wn0 + nt * 8 + 2 * (lane & 3);
            float* p = C + (size_t)row * D + col;
            p[0] = acc[mt][nt][0];
            p[1] = acc[mt][nt][1];
            p += 8 * (size_t)D;
            p[0] = acc[mt][nt][2];
            p[1] = acc[mt][nt][3];
        }
    }
}

// -------- fused: conv+SiLU, RMSNorm, RoPE, transpose; emits bf16 hi/lo ---------
__global__ void fuse_post(const float* __restrict__ cosb,
                          const float* __restrict__ sinb,
                          const float* __restrict__ wq,
                          const float* __restrict__ wk,
                          const float* __restrict__ wv,
                          const float* __restrict__ qnw,
                          const float* __restrict__ knw)
{
    const int t  = blockIdx.x;
    const int h  = blockIdx.y;
    const int hd = threadIdx.x;
    const int d  = h * HD + hd;

    float yq = 0.f, yk = 0.f, yv = 0.f;
#pragma unroll
    for (int j = 0; j < KC; j++) {
        int tt = t - (KC - 1) + j;
        if (tt >= 0) {
            size_t o = (size_t)tt * D + d;
            yq = fmaf(g_q[o], wq[d * KC + j], yq);
            yk = fmaf(g_k[o], wk[d * KC + j], yk);
            yv = fmaf(g_v[o], wv[d * KC + j], yv);
        }
    }
    yq = yq / (1.f + __expf(-yq));
    yk = yk / (1.f + __expf(-yk));
    yv = yv / (1.f + __expf(-yv));

    float vq = yq * yq, vk = yk * yk;
#pragma unroll
    for (int off = 16; off > 0; off >>= 1) {
        vq += __shfl_xor_sync(0xffffffffu, vq, off);
        vk += __shfl_xor_sync(0xffffffffu, vk, off);
    }
    __shared__ float rq[4], rk[4], sq[HD], sk[HD];
    const int w = hd >> 5;
    if ((hd & 31) == 0) { rq[w] = vq; rk[w] = vk; }
    __syncthreads();
    const float varq = (rq[0] + rq[1] + rq[2] + rq[3]) * (1.f / HD);
    const float vark = (rk[0] + rk[1] + rk[2] + rk[3]) * (1.f / HD);
    sq[hd] = yq * rsqrtf(varq + 1e-5f) * qnw[hd];
    sk[hd] = yk * rsqrtf(vark + 1e-5f) * knw[hd];
    __syncthreads();

    float oq, ok;
    if (hd < RD) {
        const float cs = cosb[t * RD + hd];
        const float sn = sinb[t * RD + hd];
        const float rqv = (hd < RD / 2) ? -sq[hd + RD / 2] : sq[hd - RD / 2];
        const float rkv = (hd < RD / 2) ? -sk[hd + RD / 2] : sk[hd - RD / 2];
        oq = -(sq[hd] * cs + rqv * sn);
        ok = -(sk[hd] * cs + rkv * sn);
    } else {
        oq = sq[hd];
        ok = sk[hd];
    }

    const float scale = 0.08838834764831845f;  // 1/sqrt(128), folded into q
    oq *= scale;

    const size_t o = ((size_t)h * T + t) * HD + hd;
    __nv_bfloat16 b;
    b = __float2bfloat16(oq); g_q2h[o] = b; g_q2l[o] = __float2bfloat16(oq - __bfloat162float(b));
    b = __float2bfloat16(ok); g_k2h[o] = b; g_k2l[o] = __float2bfloat16(ok - __bfloat162float(b));
    b = __float2bfloat16(yv); g_v2h[o] = b; g_v2l[o] = __float2bfloat16(yv - __bfloat162float(b));
}

// ---------------- flash attention v2: 128-row Q tiles, warp-local softmax ------
// grid (T/128, H), 256 threads (8 warps). Warp w owns q rows [w*16, w*16+16).
// kv tiles 64 wide, double-buffered. All softmax reductions warp-local (quad shfl).
// smem byte layout per stage: Kh | Kl | Vh | Vl, each 2*KTSZ bytes.
#define FSTR   136
#define QTSZ   (128 * FSTR)             // Q tile elems (one of hi/lo)
#define KTSZ   (64 * FSTR)              // kv tile elems
#define FSMEM  ((2 * QTSZ + 8 * KTSZ) * 2)  // 208896 bytes

__global__ __launch_bounds__(256, 1)
void flash_mma()
{
    extern __shared__ __nv_bfloat16 fsm[];

    const int tid  = threadIdx.x;
    const int lane = tid & 31;
    const int wm   = tid >> 5;             // 0..7, q-row group
    const int h    = blockIdx.y;
    const int qt   = gridDim.x - 1 - blockIdx.x;  // heavy tiles first
    const int q0   = qt * 128;

    const uint32_t sb  = smem_u32(fsm);
    const uint32_t sQh = sb;

    auto ldq = [&]() {
#pragma unroll
        for (int t = 0; t < 8; t++) {
            const int idx = t * 256 + tid;
            const int r   = idx >> 4;
            const int cc  = idx & 15;
            const uint32_t so = 2 * (r * FSTR + cc * 8);
            const size_t  go = ((size_t)h * T + q0 + r) * HD + cc * 8;
            CP16(sQh + so,            g_q2h + go);
            CP16(sQh + QTSZ * 2 + so, g_q2l + go);
        }
    };
    auto ldkv = [&](int kt2, int s) {
        const uint32_t kb = sb + 2 * (2 * QTSZ + (uint32_t)s * 4 * KTSZ);
#pragma unroll
        for (int t = 0; t < 4; t++) {
            const int idx = t * 256 + tid;
            const int r   = idx >> 4;
            const int cc  = idx & 15;
            const uint32_t so = 2 * (r * FSTR + cc * 8);
            const size_t  go = ((size_t)h * T + kt2 * 64 + r) * HD + cc * 8;
            CP16(kb + so,            g_k2h + go);
            CP16(kb + 2 * KTSZ + so, g_k2l + go);
            CP16(kb + 4 * KTSZ + so, g_v2h + go);
            CP16(kb + 6 * KTSZ + so, g_v2l + go);
        }
    };

    float acco[16][4];
#pragma unroll
    for (int nt = 0; nt < 16; nt++)
#pragma unroll
        for (int i = 0; i < 4; i++) acco[nt][i] = 0.f;
    float m0 = -1e30f, m1 = -1e30f, l0 = 0.f, l1 = 0.f;

    ldq(); ldkv(0, 0); CP_COMMIT();
    ldkv(1, 1); CP_COMMIT();

    const int r0l = wm * 16 + (lane >> 2);   // local q row (0..127)
    const int r1l = r0l + 8;
    const uint32_t qoff = 2 * ((wm * 16 + (lane & 15)) * FSTR + ((lane >> 4) << 3));
    const int krow = (lane & 7) + ((lane & 16) >> 1);
    const int rowMax = q0 + wm * 16 + 15;    // highest q row this warp owns

    const int NKV = 2 * qt + 2;

    for (int kt = 0; kt < NKV; kt++) {
        CP_WAIT(1);
        __syncthreads();

        const bool active = (kt * 64 <= rowMax);
        const uint32_t kb = sb + 2 * (2 * QTSZ + (uint32_t)(kt & 1) * 4 * KTSZ);

        if (active) {
            // ---- S = Q K^T (3-pass) ----
            float accs[8][4];
#pragma unroll
            for (int nt = 0; nt < 8; nt++)
#pragma unroll
                for (int i = 0; i < 4; i++) accs[nt][i] = 0.f;

#pragma unroll
            for (int j = 0; j < 8; j++) {
                uint32_t ah[4], al[4];
                const uint32_t qa = sQh + qoff + 2 * (j * 16);
                LDSM4(ah[0], ah[1], ah[2], ah[3], qa);
                LDSM4(al[0], al[1], al[2], al[3], qa + QTSZ * 2);
                uint32_t bh[8][2], bl[8][2];
#pragma unroll
                for (int np = 0; np < 4; np++) {
                    const uint32_t ka = kb + 2 * ((np * 16 + krow) * FSTR + j * 16 + (lane & 8));
                    LDSM4(bh[2 * np][0], bh[2 * np][1], bh[2 * np + 1][0], bh[2 * np + 1][1], ka);
                    LDSM4(bl[2 * np][0], bl[2 * np][1], bl[2 * np + 1][0], bl[2 * np + 1][1],
                          ka + 2 * KTSZ);
                }
#pragma unroll
                for (int nt = 0; nt < 8; nt++) {
                    MMA16816(accs[nt], ah, bh[nt]);
                    MMA16816(accs[nt], ah, bl[nt]);
                    MMA16816(accs[nt], al, bh[nt]);
                }
            }

            // ---- causal mask (partial tiles only) ----
            if (kt >= 2 * qt) {
                const int gr0 = q0 + r0l, gr1 = q0 + r1l;
#pragma unroll
                for (int nt = 0; nt < 8; nt++) {
                    const int c0 = kt * 64 + nt * 8 + 2 * (lane & 3);
                    if (c0     > gr0) accs[nt][0] = -1e30f;
                    if (c0 + 1 > gr0) accs[nt][1] = -1e30f;
                    if (c0     > gr1) accs[nt][2] = -1e30f;
                    if (c0 + 1 > gr1) accs[nt][3] = -1e30f;
                }
            }

            // ---- warp-local row max ----
            float mx0 = -1e30f, mx1 = -1e30f;
#pragma unroll
            for (int nt = 0; nt < 8; nt++) {
                mx0 = fmaxf(mx0, fmaxf(accs[nt][0], accs[nt][1]));
                mx1 = fmaxf(mx1, fmaxf(accs[nt][2], accs[nt][3]));
            }
            mx0 = fmaxf(mx0, __shfl_xor_sync(0xffffffffu, mx0, 1));
            mx0 = fmaxf(mx0, __shfl_xor_sync(0xffffffffu, mx0, 2));
            mx1 = fmaxf(mx1, __shfl_xor_sync(0xffffffffu, mx1, 1));
            mx1 = fmaxf(mx1, __shfl_xor_sync(0xffffffffu, mx1, 2));
            const float mn0 = fmaxf(m0, mx0), mn1 = fmaxf(m1, mx1);
            const float c0 = __expf(m0 - mn0), c1 = __expf(m1 - mn1);

            // ---- p = exp(s - m), row sums ----
            float p[8][4];
            float ps0 = 0.f, ps1 = 0.f;
#pragma unroll
            for (int nt = 0; nt < 8; nt++) {
                p[nt][0] = __expf(accs[nt][0] - mn0); ps0 += p[nt][0];
                p[nt][1] = __expf(accs[nt][1] - mn0); ps0 += p[nt][1];
                p[nt][2] = __expf(accs[nt][2] - mn1); ps1 += p[nt][2];
                p[nt][3] = __expf(accs[nt][3] - mn1); ps1 += p[nt][3];
            }
            ps0 += __shfl_xor_sync(0xffffffffu, ps0, 1);
            ps0 += __shfl_xor_sync(0xffffffffu, ps0, 2);
            ps1 += __shfl_xor_sync(0xffffffffu, ps1, 1);
            ps1 += __shfl_xor_sync(0xffffffffu, ps1, 2);
            l0 = l0 * c0 + ps0;
            l1 = l1 * c1 + ps1;
            m0 = mn0; m1 = mn1;

#pragma unroll
            for (int nt = 0; nt < 16; nt++) {
                acco[nt][0] *= c0; acco[nt][1] *= c0;
                acco[nt][2] *= c1; acco[nt][3] *= c1;
            }

            // ---- P hi/lo A-fragments ----
            uint32_t pha[4][4], pla[4][4];
#pragma unroll
            for (int j = 0; j < 4; j++) {
                split2(p[2 * j][0],     p[2 * j][1],     pha[j][0], pla[j][0]);
                split2(p[2 * j][2],     p[2 * j][3],     pha[j][1], pla[j][1]);
                split2(p[2 * j + 1][0], p[2 * j + 1][1], pha[j][2], pla[j][2]);
                split2(p[2 * j + 1][2], p[2 * j + 1][3], pha[j][3], pla[j][3]);
            }

            // ---- O += P V (3-pass), V via ldmatrix.trans ----
            const uint32_t vb = kb + 4 * KTSZ;   // V-hi at byte offset 4*KTSZ (2 tiles)
#pragma unroll
            for (int j = 0; j < 4; j++) {
                const int k0 = j * 16 + (lane & 15);
#pragma unroll
                for (int np = 0; np < 8; np++) {
                    const uint32_t va = vb + 2 * (k0 * FSTR + np * 16 + ((lane >> 4) << 3));
                    uint32_t vh[4], vl[4];
                    LDSM4T(vh[0], vh[1], vh[2], vh[3], va);
                    LDSM4T(vl[0], vl[1], vl[2], vl[3], va + 2 * KTSZ);
                    MMA16816(acco[2 * np],     pha[j], vh);
                    MMA16816(acco[2 * np],     pha[j], vl);
                    MMA16816(acco[2 * np],     pla[j], vh);
                    MMA16816(acco[2 * np + 1], pha[j], vh + 2);
                    MMA16816(acco[2 * np + 1], pha[j], vl + 2);
                    MMA16816(acco[2 * np + 1], pla[j], vh + 2);
                }
            }
        }

        __syncthreads();
        if (kt + 2 < NKV) ldkv(kt + 2, kt & 1);
        CP_COMMIT();
    }

    // ---- normalize, emit bf16 hi/lo (warp-private rows, no combine) ----
    const float il0 = 1.f / l0, il1 = 1.f / l1;
#pragma unroll
    for (int nt = 0; nt < 16; nt++) {
        const int col = nt * 8 + 2 * (lane & 3);
        const float v0 = acco[nt][0] * il0;
        const float v1 = acco[nt][1] * il0;
        const float v2 = acco[nt][2] * il1;
        const float v3 = acco[nt][3] * il1;
        uint32_t hi, lo;
        const size_t o0 = (size_t)(q0 + r0l) * D + h * HD + col;
        const size_t o1 = (size_t)(q0 + r1l) * D + h * HD + col;
        split2(v0, v1, hi, lo);
        *(uint32_t*)&g_ah[o0] = hi; *(uint32_t*)&g_al[o0] = lo;
        split2(v2, v3, hi, lo);
        *(uint32_t*)&g_ah[o1] = hi; *(uint32_t*)&g_al[o1] = lo;
    }
}

// -----------------------------------------------------------------------------
extern "C" void kernel_launch(void* const* d_in, const int* in_sizes, int n_in,
                              void* d_out, int out_size)
{
    const float* x    = (const float*)d_in[0];
    const float* cosb = (const float*)d_in[1];
    const float* sinb = (const float*)d_in[2];
    const float* Wq   = (const float*)d_in[3];
    const float* Wk   = (const float*)d_in[4];
    const float* Wv   = (const float*)d_in[5];
    const float* Wo   = (const float*)d_in[6];
    const float* wq   = (const float*)d_in[7];
    const float* wk   = (const float*)d_in[8];
    const float* wv   = (const float*)d_in[9];
    const float* qnw  = (const float*)d_in[10];
    const float* knw  = (const float*)d_in[11];
    float* out = (float*)d_out;

    float *pq, *pk, *pv;
    __nv_bfloat16 *pxh, *pxl, *pwh, *pwl, *pah, *pal;
    cudaGetSymbolAddress((void**)&pq, g_q);
    cudaGetSymbolAddress((void**)&pk, g_k);
    cudaGetSymbolAddress((void**)&pv, g_v);
    cudaGetSymbolAddress((void**)&pxh, g_xh);
    cudaGetSymbolAddress((void**)&pxl, g_xl);
    cudaGetSymbolAddress((void**)&pwh, g_wh);
    cudaGetSymbolAddress((void**)&pwl, g_wl);
    cudaGetSymbolAddress((void**)&pah, g_ah);
    cudaGetSymbolAddress((void**)&pal, g_al);

    __nv_bfloat16* wh[4];
    __nv_bfloat16* wl[4];
    for (int i = 0; i < 4; i++) { wh[i] = pwh + (size_t)i * D * D; wl[i] = pwl + (size_t)i * D * D; }

    cudaFuncSetAttribute(gemm_bf16s, cudaFuncAttributeMaxDynamicSharedMemorySize, GEMM_SMEM);
    cudaFuncSetAttribute(flash_mma,  cudaFuncAttributeMaxDynamicSharedMemorySize, FSMEM);

    // 0) split x, Wq, Wk, Wv, Wo into bf16 hi/lo
    split_bf16<<<dim3(256, 1, 5), 256>>>(x, pxh, pxl,
                                         Wq, wh[0], wl[0],
                                         Wk, wh[1], wl[1],
                                         Wv, wh[2], wl[2],
                                         Wo, wh[3], wl[3]);

    // 1) QKV projections
    gemm_bf16s<<<dim3(16, 16, 3), 256, GEMM_SMEM>>>(pxh, pxl,
                                                    wh[0], wl[0], wh[1], wl[1], wh[2], wl[2],
                                                    pq, pk, pv);

    // 2) conv + SiLU + RMSNorm + RoPE + transpose (emits bf16 hi/lo, q scaled)
    fuse_post<<<dim3(T, H), HD>>>(cosb, sinb, wq, wk, wv, qnw, knw);

    // 3) causal flash attention (tensor cores, 128-row q tiles)
    flash_mma<<<dim3(T / 128, H), 256, FSMEM>>>();

    // 4) O-proj -> d_out (reads bf16 hi/lo attn directly)
    gemm_bf16s<<<dim3(16, 16, 1), 256, GEMM_SMEM>>>(pah, pal,
                                                    wh[3], wl[3], wh[3], wl[3], wh[3], wl[3],
                                                    out, out, out);
}

// round 7
// speedup vs baseline: 4.5691x; 1.2498x over previous
#include <cuda_runtime.h>
#include <cuda_bf16.h>
#include <math.h>
#include <stdint.h>

#define T 2048
#define D 2048
#define H 16
#define HD 128
#define RD 64
#define KC 4

// ---------------- scratch (device globals) -----------------------------------
__device__ float g_q[T * D];
__device__ float g_k[T * D];
__device__ float g_v[T * D];

__device__ __nv_bfloat16 g_xh[T * D], g_xl[T * D];
__device__ __nv_bfloat16 g_wh[4][D * D], g_wl[4][D * D];  // Wq,Wk,Wv,Wo
__device__ __nv_bfloat16 g_ah[T * D], g_al[T * D];        // attn out hi/lo

// flash inputs, bf16 hi/lo, [H][T][HD]
__device__ __nv_bfloat16 g_q2h[T * D], g_q2l[T * D];
__device__ __nv_bfloat16 g_k2h[T * D], g_k2l[T * D];
__device__ __nv_bfloat16 g_v2h[T * D], g_v2l[T * D];

// ---------------- PTX helpers --------------------------------------------------
__device__ __forceinline__ uint32_t smem_u32(const void* p) {
    uint32_t a;
    asm("{ .reg .u64 t; cvta.to.shared.u64 t, %1; cvt.u32.u64 %0, t; }" : "=r"(a) : "l"(p));
    return a;
}

#define CP16(dst, src) \
    asm volatile("cp.async.cg.shared.global [%0], [%1], 16;" :: "r"(dst), "l"(src))
#define CP_COMMIT() asm volatile("cp.async.commit_group;" ::: "memory")
#define CP_WAIT(n)  asm volatile("cp.async.wait_group %0;" :: "n"(n) : "memory")

#define LDSM4(r0, r1, r2, r3, addr)                                      \
    asm volatile("ldmatrix.sync.aligned.m8n8.x4.shared.b16 {%0,%1,%2,%3}, [%4];" \
        : "=r"(r0), "=r"(r1), "=r"(r2), "=r"(r3) : "r"(addr))

#define LDSM4T(r0, r1, r2, r3, addr)                                     \
    asm volatile("ldmatrix.sync.aligned.m8n8.x4.trans.shared.b16 {%0,%1,%2,%3}, [%4];" \
        : "=r"(r0), "=r"(r1), "=r"(r2), "=r"(r3) : "r"(addr))

#define MMA16816(d, a, b)                                                \
    asm volatile("mma.sync.aligned.m16n8k16.row.col.f32.bf16.bf16.f32 "  \
        "{%0,%1,%2,%3}, {%4,%5,%6,%7}, {%8,%9}, {%0,%1,%2,%3};"          \
        : "+f"((d)[0]), "+f"((d)[1]), "+f"((d)[2]), "+f"((d)[3])         \
        : "r"((a)[0]), "r"((a)[1]), "r"((a)[2]), "r"((a)[3]),            \
          "r"((b)[0]), "r"((b)[1]))

__device__ __forceinline__ void split2(float a, float b, uint32_t& hi, uint32_t& lo) {
    __nv_bfloat162 h = __floats2bfloat162_rn(a, b);
    __nv_bfloat162 l = __floats2bfloat162_rn(a - __low2float(h), b - __high2float(h));
    hi = *(uint32_t*)&h;
    lo = *(uint32_t*)&l;
}

// ---------------- fp32 -> bf16 hi/lo split (inputs) ----------------------------
__global__ void split_bf16(const float* __restrict__ s0, __nv_bfloat16* h0, __nv_bfloat16* l0,
                           const float* __restrict__ s1, __nv_bfloat16* h1, __nv_bfloat16* l1,
                           const float* __restrict__ s2, __nv_bfloat16* h2, __nv_bfloat16* l2,
                           const float* __restrict__ s3, __nv_bfloat16* h3, __nv_bfloat16* l3,
                           const float* __restrict__ s4, __nv_bfloat16* h4, __nv_bfloat16* l4)
{
    const float* s; __nv_bfloat16 *h, *l;
    switch (blockIdx.z) {
        case 0:  s = s0; h = h0; l = l0; break;
        case 1:  s = s1; h = h1; l = l1; break;
        case 2:  s = s2; h = h2; l = l2; break;
        case 3:  s = s3; h = h3; l = l3; break;
        default: s = s4; h = h4; l = l4; break;
    }
    const int n4 = T * D / 4;
    for (int i = blockIdx.x * blockDim.x + threadIdx.x; i < n4; i += gridDim.x * blockDim.x) {
        float4 v = ((const float4*)s)[i];
        __nv_bfloat162 h01 = __floats2bfloat162_rn(v.x, v.y);
        __nv_bfloat162 h23 = __floats2bfloat162_rn(v.z, v.w);
        __nv_bfloat162 l01 = __floats2bfloat162_rn(v.x - __low2float(h01), v.y - __high2float(h01));
        __nv_bfloat162 l23 = __floats2bfloat162_rn(v.z - __low2float(h23), v.w - __high2float(h23));
        ((__nv_bfloat162*)h)[2 * i]     = h01;
        ((__nv_bfloat162*)h)[2 * i + 1] = h23;
        ((__nv_bfloat162*)l)[2 * i]     = l01;
        ((__nv_bfloat162*)l)[2 * i + 1] = l23;
    }
}

// ---------------- bf16-split GEMM (NT), 3-stage swizzled, 2 CTA/SM ------------
// rows are 32 bf16 = 64B; 16B chunk swizzle: phys = chunk ^ ((row>>1)&3).
#define BK      32
#define NCK     (D / BK)
#define TILE_B  (128 * 64)        // bytes per tile (128 rows x 64B)
#define STAGE_B (4 * TILE_B)      // Ah,Al,Bh,Bl = 32768 B
#define GEMM_SMEM (3 * STAGE_B)   // 98304 B -> 2 CTAs/SM
#define SWZ16(row, ch) ((((ch) ^ (((row) >> 1) & 3))) * 16)

__global__ __launch_bounds__(256, 2)
void gemm_bf16s(const __nv_bfloat16* __restrict__ Ah_, const __nv_bfloat16* __restrict__ Al_,
                const __nv_bfloat16* __restrict__ Bh0, const __nv_bfloat16* __restrict__ Bl0,
                const __nv_bfloat16* __restrict__ Bh1, const __nv_bfloat16* __restrict__ Bl1,
                const __nv_bfloat16* __restrict__ Bh2, const __nv_bfloat16* __restrict__ Bl2,
                float* __restrict__ C0, float* __restrict__ C1, float* __restrict__ C2)
{
    const __nv_bfloat16* Bh_ = (blockIdx.z == 0) ? Bh0 : ((blockIdx.z == 1) ? Bh1 : Bh2);
    const __nv_bfloat16* Bl_ = (blockIdx.z == 0) ? Bl0 : ((blockIdx.z == 1) ? Bl1 : Bl2);
    float*               C   = (blockIdx.z == 0) ? C0  : ((blockIdx.z == 1) ? C1  : C2);

    extern __shared__ __nv_bfloat16 sm[];
    const uint32_t sbase = smem_u32(sm);

    const int tid  = threadIdx.x;
    const int lane = tid & 31;
    const int warp = tid >> 5;
    const int wm0  = (warp & 3) * 32;
    const int wn0  = (warp >> 2) * 64;
    const int brow = blockIdx.y * 128;
    const int bcol = blockIdx.x * 128;

    const int rld = tid >> 2;   // 0..63
    const int cld = tid & 3;    // logical 16B chunk

    auto load_chunk = [&](int c, int slot) {
        const int k0 = c * BK;
        const uint32_t s0 = sbase + (uint32_t)slot * STAGE_B;
#pragma unroll
        for (int t = 0; t < 2; t++) {
            const int r = rld + t * 64;
            const uint32_t so = s0 + r * 64 + SWZ16(r, cld);
            const size_t ga = (size_t)(brow + r) * D + k0 + cld * 8;
            const size_t gb = (size_t)(bcol + r) * D + k0 + cld * 8;
            CP16(so,              Ah_ + ga);
            CP16(so + TILE_B,     Al_ + ga);
            CP16(so + 2 * TILE_B, Bh_ + gb);
            CP16(so + 3 * TILE_B, Bl_ + gb);
        }
    };

    float acc[2][8][4];
#pragma unroll
    for (int mt = 0; mt < 2; mt++)
#pragma unroll
        for (int nt = 0; nt < 8; nt++)
#pragma unroll
            for (int i = 0; i < 4; i++) acc[mt][nt][i] = 0.f;

    load_chunk(0, 0); CP_COMMIT();
    load_chunk(1, 1); CP_COMMIT();

    const int arow = wm0 + (lane & 15);
    const int achk = lane >> 4;                 // 0/1
    const int nrow = wn0 + (lane & 7) + ((lane & 16) >> 1);
    const int bchk = (lane & 8) >> 3;           // 0/1

    for (int c = 0; c < NCK; c++) {
        CP_WAIT(1);
        __syncthreads();

        const uint32_t sbm = sbase + (uint32_t)(c % 3) * STAGE_B;
#pragma unroll
        for (int ks = 0; ks < 2; ks++) {
            uint32_t ah[2][4], al[2][4], bh[8][2], bl[8][2];
#pragma unroll
            for (int mt = 0; mt < 2; mt++) {
                const int lrow = arow + mt * 16;
                const uint32_t ad = sbm + lrow * 64 + SWZ16(lrow, ks * 2 + achk);
                LDSM4(ah[mt][0], ah[mt][1], ah[mt][2], ah[mt][3], ad);
                LDSM4(al[mt][0], al[mt][1], al[mt][2], al[mt][3], ad + TILE_B);
            }
#pragma unroll
            for (int np = 0; np < 4; np++) {
                const int brw = nrow + np * 16;
                const uint32_t bd = sbm + 2 * TILE_B + brw * 64 + SWZ16(brw, ks * 2 + bchk);
                LDSM4(bh[2 * np][0], bh[2 * np][1], bh[2 * np + 1][0], bh[2 * np + 1][1], bd);
                LDSM4(bl[2 * np][0], bl[2 * np][1], bl[2 * np + 1][0], bl[2 * np + 1][1],
                      bd + TILE_B);
            }
#pragma unroll
            for (int mt = 0; mt < 2; mt++)
#pragma unroll
                for (int nt = 0; nt < 8; nt++) {
                    MMA16816(acc[mt][nt], ah[mt], bh[nt]);
                    MMA16816(acc[mt][nt], ah[mt], bl[nt]);
                    MMA16816(acc[mt][nt], al[mt], bh[nt]);
                }
        }

        if (c + 2 < NCK) load_chunk(c + 2, (c + 2) % 3);
        CP_COMMIT();
    }

#pragma unroll
    for (int mt = 0; mt < 2; mt++) {
        const int row = brow + wm0 + mt * 16 + (lane >> 2);
#pragma unroll
        for (int nt = 0; nt < 8; nt++) {
            const int col = bcol + wn0 + nt * 8 + 2 * (lane & 3);
            float* p = C + (size_t)row * D + col;
            p[0] = acc[mt][nt][0];
            p[1] = acc[mt][nt][1];
            p += 8 * (size_t)D;
            p[0] = acc[mt][nt][2];
            p[1] = acc[mt][nt][3];
        }
    }
}

// -------- fused: conv+SiLU, RMSNorm, RoPE, transpose; emits bf16 hi/lo ---------
__global__ void fuse_post(const float* __restrict__ cosb,
                          const float* __restrict__ sinb,
                          const float* __restrict__ wq,
                          const float* __restrict__ wk,
                          const float* __restrict__ wv,
                          const float* __restrict__ qnw,
                          const float* __restrict__ knw)
{
    const int t  = blockIdx.x;
    const int h  = blockIdx.y;
    const int hd = threadIdx.x;
    const int d  = h * HD + hd;

    float yq = 0.f, yk = 0.f, yv = 0.f;
#pragma unroll
    for (int j = 0; j < KC; j++) {
        int tt = t - (KC - 1) + j;
        if (tt >= 0) {
            size_t o = (size_t)tt * D + d;
            yq = fmaf(g_q[o], wq[d * KC + j], yq);
            yk = fmaf(g_k[o], wk[d * KC + j], yk);
            yv = fmaf(g_v[o], wv[d * KC + j], yv);
        }
    }
    yq = yq / (1.f + __expf(-yq));
    yk = yk / (1.f + __expf(-yk));
    yv = yv / (1.f + __expf(-yv));

    float vq = yq * yq, vk = yk * yk;
#pragma unroll
    for (int off = 16; off > 0; off >>= 1) {
        vq += __shfl_xor_sync(0xffffffffu, vq, off);
        vk += __shfl_xor_sync(0xffffffffu, vk, off);
    }
    __shared__ float rq[4], rk[4], sq[HD], sk[HD];
    const int w = hd >> 5;
    if ((hd & 31) == 0) { rq[w] = vq; rk[w] = vk; }
    __syncthreads();
    const float varq = (rq[0] + rq[1] + rq[2] + rq[3]) * (1.f / HD);
    const float vark = (rk[0] + rk[1] + rk[2] + rk[3]) * (1.f / HD);
    sq[hd] = yq * rsqrtf(varq + 1e-5f) * qnw[hd];
    sk[hd] = yk * rsqrtf(vark + 1e-5f) * knw[hd];
    __syncthreads();

    float oq, ok;
    if (hd < RD) {
        const float cs = cosb[t * RD + hd];
        const float sn = sinb[t * RD + hd];
        const float rqv = (hd < RD / 2) ? -sq[hd + RD / 2] : sq[hd - RD / 2];
        const float rkv = (hd < RD / 2) ? -sk[hd + RD / 2] : sk[hd - RD / 2];
        oq = -(sq[hd] * cs + rqv * sn);
        ok = -(sk[hd] * cs + rkv * sn);
    } else {
        oq = sq[hd];
        ok = sk[hd];
    }

    const float scale = 0.08838834764831845f;  // 1/sqrt(128), folded into q
    oq *= scale;

    const size_t o = ((size_t)h * T + t) * HD + hd;
    __nv_bfloat16 b;
    b = __float2bfloat16(oq); g_q2h[o] = b; g_q2l[o] = __float2bfloat16(oq - __bfloat162float(b));
    b = __float2bfloat16(ok); g_k2h[o] = b; g_k2l[o] = __float2bfloat16(ok - __bfloat162float(b));
    b = __float2bfloat16(yv); g_v2h[o] = b; g_v2l[o] = __float2bfloat16(yv - __bfloat162float(b));
}

// ---------------- flash attention v3: 64-row Q, 32-row KV, 2 CTA/SM -----------
// grid (T/64, H), 128 threads (4 warps). Warp w owns q rows [w*16, w*16+16).
// kv tiles 32 wide, double-buffered. Softmax warp-local (quad shfl).
#define FSTR   136
#define FQT    (64 * FSTR)              // Q tile elems (hi or lo)
#define FKT    (32 * FSTR)              // kv tile elems
#define FSMEM  ((2 * FQT + 8 * FKT) * 2)  // 104448 B -> 2 CTAs/SM

__global__ __launch_bounds__(128, 2)
void flash_mma()
{
    extern __shared__ __nv_bfloat16 fsm[];

    const int tid  = threadIdx.x;
    const int lane = tid & 31;
    const int wm   = tid >> 5;             // 0..3
    const int h    = blockIdx.y;
    const int qt   = gridDim.x - 1 - blockIdx.x;  // heavy tiles first
    const int q0   = qt * 64;

    const uint32_t sb = smem_u32(fsm);

    auto ldq = [&]() {
#pragma unroll
        for (int t = 0; t < 8; t++) {
            const int idx = t * 128 + tid;
            const int r   = idx >> 4;        // 0..63
            const int cc  = idx & 15;
            const uint32_t so = 2 * (r * FSTR + cc * 8);
            const size_t  go = ((size_t)h * T + q0 + r) * HD + cc * 8;
            CP16(sb + so,           g_q2h + go);
            CP16(sb + 2 * FQT + so, g_q2l + go);
        }
    };
    auto ldkv = [&](int kt2, int s) {
        const uint32_t kb = sb + 2 * (2 * FQT + (uint32_t)s * 4 * FKT);
#pragma unroll
        for (int t = 0; t < 4; t++) {
            const int idx = t * 128 + tid;
            const int r   = idx >> 4;        // 0..31
            const int cc  = idx & 15;
            const uint32_t so = 2 * (r * FSTR + cc * 8);
            const size_t  go = ((size_t)h * T + kt2 * 32 + r) * HD + cc * 8;
            CP16(kb + so,           g_k2h + go);
            CP16(kb + 2 * FKT + so, g_k2l + go);
            CP16(kb + 4 * FKT + so, g_v2h + go);
            CP16(kb + 6 * FKT + so, g_v2l + go);
        }
    };

    float acco[16][4];
#pragma unroll
    for (int nt = 0; nt < 16; nt++)
#pragma unroll
        for (int i = 0; i < 4; i++) acco[nt][i] = 0.f;
    float m0 = -1e30f, m1 = -1e30f, l0 = 0.f, l1 = 0.f;

    ldq(); ldkv(0, 0); CP_COMMIT();
    ldkv(1, 1); CP_COMMIT();

    const int r0l = wm * 16 + (lane >> 2);   // local q row (0..63)
    const int r1l = r0l + 8;
    const uint32_t qoff = 2 * ((wm * 16 + (lane & 15)) * FSTR + ((lane >> 4) << 3));
    const int krow = (lane & 7) + ((lane & 16) >> 1);
    const int rowMax = q0 + wm * 16 + 15;

    const int NKV = 2 * qt + 2;   // kv tiles of 32

    for (int kt = 0; kt < NKV; kt++) {
        CP_WAIT(1);
        __syncthreads();

        const bool active = (kt * 32 <= rowMax);
        const uint32_t kb = sb + 2 * (2 * FQT + (uint32_t)(kt & 1) * 4 * FKT);

        if (active) {
            // ---- S = Q K^T (3-pass), 16x32 per warp ----
            float accs[4][4];
#pragma unroll
            for (int nt = 0; nt < 4; nt++)
#pragma unroll
                for (int i = 0; i < 4; i++) accs[nt][i] = 0.f;

#pragma unroll
            for (int j = 0; j < 8; j++) {
                uint32_t ah[4], al[4];
                const uint32_t qa = sb + qoff + 2 * (j * 16);
                LDSM4(ah[0], ah[1], ah[2], ah[3], qa);
                LDSM4(al[0], al[1], al[2], al[3], qa + 2 * FQT);
                uint32_t bh[4][2], bl[4][2];
#pragma unroll
                for (int np = 0; np < 2; np++) {
                    const uint32_t ka = kb + 2 * ((np * 16 + krow) * FSTR + j * 16 + (lane & 8));
                    LDSM4(bh[2 * np][0], bh[2 * np][1], bh[2 * np + 1][0], bh[2 * np + 1][1], ka);
                    LDSM4(bl[2 * np][0], bl[2 * np][1], bl[2 * np + 1][0], bl[2 * np + 1][1],
                          ka + 2 * FKT);
                }
#pragma unroll
                for (int nt = 0; nt < 4; nt++) {
                    MMA16816(accs[nt], ah, bh[nt]);
                    MMA16816(accs[nt], ah, bl[nt]);
                    MMA16816(accs[nt], al, bh[nt]);
                }
            }

            // ---- causal mask (partial tiles only) ----
            if (kt >= 2 * qt) {
                const int gr0 = q0 + r0l, gr1 = q0 + r1l;
#pragma unroll
                for (int nt = 0; nt < 4; nt++) {
                    const int c0 = kt * 32 + nt * 8 + 2 * (lane & 3);
                    if (c0     > gr0) accs[nt][0] = -1e30f;
                    if (c0 + 1 > gr0) accs[nt][1] = -1e30f;
                    if (c0     > gr1) accs[nt][2] = -1e30f;
                    if (c0 + 1 > gr1) accs[nt][3] = -1e30f;
                }
            }

            // ---- warp-local row max ----
            float mx0 = -1e30f, mx1 = -1e30f;
#pragma unroll
            for (int nt = 0; nt < 4; nt++) {
                mx0 = fmaxf(mx0, fmaxf(accs[nt][0], accs[nt][1]));
                mx1 = fmaxf(mx1, fmaxf(accs[nt][2], accs[nt][3]));
            }
            mx0 = fmaxf(mx0, __shfl_xor_sync(0xffffffffu, mx0, 1));
            mx0 = fmaxf(mx0, __shfl_xor_sync(0xffffffffu, mx0, 2));
            mx1 = fmaxf(mx1, __shfl_xor_sync(0xffffffffu, mx1, 1));
            mx1 = fmaxf(mx1, __shfl_xor_sync(0xffffffffu, mx1, 2));
            const float mn0 = fmaxf(m0, mx0), mn1 = fmaxf(m1, mx1);
            const float c0 = __expf(m0 - mn0), c1 = __expf(m1 - mn1);

            // ---- p = exp(s - m), row sums ----
            float p[4][4];
            float ps0 = 0.f, ps1 = 0.f;
#pragma unroll
            for (int nt = 0; nt < 4; nt++) {
                p[nt][0] = __expf(accs[nt][0] - mn0); ps0 += p[nt][0];
                p[nt][1] = __expf(accs[nt][1] - mn0); ps0 += p[nt][1];
                p[nt][2] = __expf(accs[nt][2] - mn1); ps1 += p[nt][2];
                p[nt][3] = __expf(accs[nt][3] - mn1); ps1 += p[nt][3];
            }
            ps0 += __shfl_xor_sync(0xffffffffu, ps0, 1);
            ps0 += __shfl_xor_sync(0xffffffffu, ps0, 2);
            ps1 += __shfl_xor_sync(0xffffffffu, ps1, 1);
            ps1 += __shfl_xor_sync(0xffffffffu, ps1, 2);
            l0 = l0 * c0 + ps0;
            l1 = l1 * c1 + ps1;
            m0 = mn0; m1 = mn1;

#pragma unroll
            for (int nt = 0; nt < 16; nt++) {
                acco[nt][0] *= c0; acco[nt][1] *= c0;
                acco[nt][2] *= c1; acco[nt][3] *= c1;
            }

            // ---- P hi/lo A-fragments (16x32 -> 2 k-frags) ----
            uint32_t pha[2][4], pla[2][4];
#pragma unroll
            for (int j = 0; j < 2; j++) {
                split2(p[2 * j][0],     p[2 * j][1],     pha[j][0], pla[j][0]);
                split2(p[2 * j][2],     p[2 * j][3],     pha[j][1], pla[j][1]);
                split2(p[2 * j + 1][0], p[2 * j + 1][1], pha[j][2], pla[j][2]);
                split2(p[2 * j + 1][2], p[2 * j + 1][3], pha[j][3], pla[j][3]);
            }

            // ---- O += P V (3-pass), V via ldmatrix.trans ----
            const uint32_t vb = kb + 4 * FKT;   // V-hi byte offset
#pragma unroll
            for (int j = 0; j < 2; j++) {
                const int k0 = j * 16 + (lane & 15);   // 0..31
#pragma unroll
                for (int np = 0; np < 8; np++) {
                    const uint32_t va = vb + 2 * (k0 * FSTR + np * 16 + ((lane >> 4) << 3));
                    uint32_t vh[4], vl[4];
                    LDSM4T(vh[0], vh[1], vh[2], vh[3], va);
                    LDSM4T(vl[0], vl[1], vl[2], vl[3], va + 2 * FKT);
                    MMA16816(acco[2 * np],     pha[j], vh);
                    MMA16816(acco[2 * np],     pha[j], vl);
                    MMA16816(acco[2 * np],     pla[j], vh);
                    MMA16816(acco[2 * np + 1], pha[j], vh + 2);
                    MMA16816(acco[2 * np + 1], pha[j], vl + 2);
                    MMA16816(acco[2 * np + 1], pla[j], vh + 2);
                }
            }
        }

        __syncthreads();
        if (kt + 2 < NKV) ldkv(kt + 2, kt & 1);
        CP_COMMIT();
    }

    // ---- normalize, emit bf16 hi/lo (warp-private rows) ----
    const float il0 = 1.f / l0, il1 = 1.f / l1;
#pragma unroll
    for (int nt = 0; nt < 16; nt++) {
        const int col = nt * 8 + 2 * (lane & 3);
        const float v0 = acco[nt][0] * il0;
        const float v1 = acco[nt][1] * il0;
        const float v2 = acco[nt][2] * il1;
        const float v3 = acco[nt][3] * il1;
        uint32_t hi, lo;
        const size_t o0 = (size_t)(q0 + r0l) * D + h * HD + col;
        const size_t o1 = (size_t)(q0 + r1l) * D + h * HD + col;
        split2(v0, v1, hi, lo);
        *(uint32_t*)&g_ah[o0] = hi; *(uint32_t*)&g_al[o0] = lo;
        split2(v2, v3, hi, lo);
        *(uint32_t*)&g_ah[o1] = hi; *(uint32_t*)&g_al[o1] = lo;
    }
}

// -----------------------------------------------------------------------------
extern "C" void kernel_launch(void* const* d_in, const int* in_sizes, int n_in,
                              void* d_out, int out_size)
{
    const float* x    = (const float*)d_in[0];
    const float* cosb = (const float*)d_in[1];
    const float* sinb = (const float*)d_in[2];
    const float* Wq   = (const float*)d_in[3];
    const float* Wk   = (const float*)d_in[4];
    const float* Wv   = (const float*)d_in[5];
    const float* Wo   = (const float*)d_in[6];
    const float* wq   = (const float*)d_in[7];
    const float* wk   = (const float*)d_in[8];
    const float* wv   = (const float*)d_in[9];
    const float* qnw  = (const float*)d_in[10];
    const float* knw  = (const float*)d_in[11];
    float* out = (float*)d_out;

    float *pq, *pk, *pv;
    __nv_bfloat16 *pxh, *pxl, *pwh, *pwl, *pah, *pal;
    cudaGetSymbolAddress((void**)&pq, g_q);
    cudaGetSymbolAddress((void**)&pk, g_k);
    cudaGetSymbolAddress((void**)&pv, g_v);
    cudaGetSymbolAddress((void**)&pxh, g_xh);
    cudaGetSymbolAddress((void**)&pxl, g_xl);
    cudaGetSymbolAddress((void**)&pwh, g_wh);
    cudaGetSymbolAddress((void**)&pwl, g_wl);
    cudaGetSymbolAddress((void**)&pah, g_ah);
    cudaGetSymbolAddress((void**)&pal, g_al);

    __nv_bfloat16* wh[4];
    __nv_bfloat16* wl[4];
    for (int i = 0; i < 4; i++) { wh[i] = pwh + (size_t)i * D * D; wl[i] = pwl + (size_t)i * D * D; }

    cudaFuncSetAttribute(gemm_bf16s, cudaFuncAttributeMaxDynamicSharedMemorySize, GEMM_SMEM);
    cudaFuncSetAttribute(flash_mma,  cudaFuncAttributeMaxDynamicSharedMemorySize, FSMEM);

    // 0) split x, Wq, Wk, Wv, Wo into bf16 hi/lo
    split_bf16<<<dim3(256, 1, 5), 256>>>(x, pxh, pxl,
                                         Wq, wh[0], wl[0],
                                         Wk, wh[1], wl[1],
                                         Wv, wh[2], wl[2],
                                         Wo, wh[3], wl[3]);

    // 1) QKV projections
    gemm_bf16s<<<dim3(16, 16, 3), 256, GEMM_SMEM>>>(pxh, pxl,
                                                    wh[0], wl[0], wh[1], wl[1], wh[2], wl[2],
                                                    pq, pk, pv);

    // 2) conv + SiLU + RMSNorm + RoPE + transpose (emits bf16 hi/lo, q scaled)
    fuse_post<<<dim3(T, H), HD>>>(cosb, sinb, wq, wk, wv, qnw, knw);

    // 3) causal flash attention (tensor cores, 64-row q tiles, 2 CTA/SM)
    flash_mma<<<dim3(T / 64, H), 128, FSMEM>>>();

    // 4) O-proj -> d_out (reads bf16 hi/lo attn directly)
    gemm_bf16s<<<dim3(16, 16, 1), 256, GEMM_SMEM>>>(pah, pal,
                                                    wh[3], wl[3], wh[3], wl[3], wh[3], wl[3],
                                                    out, out, out);
}